// round 3
// baseline (speedup 1.0000x reference)
#include <cuda_runtime.h>
#include <math.h>

#define TWO_PI_F 6.28318530717958647692f
#define PI_F     3.14159265358979323846f
#define INV_PI_F 0.31830988618367094f

#define PSZ   8
#define HH    64
#define WW    64
#define HPN   57
#define NPP   (HPN*HPN)        // 3249
#define NBATCH 2
#define NPTOT (NBATCH*NPP)     // 6498
#define NV    31
#define CINN  32
#define NPIX  (HH*WW)          // 4096
#define NSTAT 8192

// ---------------- device scratch ----------------
__device__ float  g_y[NBATCH*3*NPIX];
__device__ float4 g_xr4[NBATCH*NPIX];
__device__ float4 g_ps4[NPTOT];
__device__ float  g_params[NBATCH*5*NPP];
__device__ float  g_smoothed[NBATCH*3*NPIX];
__device__ float  g_gb[NBATCH*NPIX];
__device__ float  g_yb[NBATCH*NPIX];
__device__ float  g_yi[NBATCH*NPIX];
__device__ float  g_stats[16];

// ---------------- packed f32x2 helpers ----------------
typedef unsigned long long f2;
__device__ __forceinline__ f2 pk(float lo, float hi) {
    f2 r; asm("mov.b64 %0,{%1,%2};" : "=l"(r) : "f"(lo), "f"(hi)); return r;
}
__device__ __forceinline__ void upk(f2 v, float& lo, float& hi) {
    asm("mov.b64 {%0,%1},%2;" : "=f"(lo), "=f"(hi) : "l"(v));
}
__device__ __forceinline__ f2 fma2(f2 a, f2 b, f2 c) {
    f2 r; asm("fma.rn.f32x2 %0,%1,%2,%3;" : "=l"(r) : "l"(a), "l"(b), "l"(c)); return r;
}
__device__ __forceinline__ f2 mul2(f2 a, f2 b) {
    f2 r; asm("mul.rn.f32x2 %0,%1,%2;" : "=l"(r) : "l"(a), "l"(b)); return r;
}
__device__ __forceinline__ f2 add2(f2 a, f2 b) {
    f2 r; asm("add.rn.f32x2 %0,%1,%2;" : "=l"(r) : "l"(a), "l"(b)); return r;
}

// ---------------- scalar helpers ----------------
__device__ __forceinline__ float mod2pi(float v) {
    float m = fmodf(v, TWO_PI_F);
    return (m < 0.0f) ? m + TWO_PI_F : m;
}
__device__ __forceinline__ float pow35(float u) {
    float u2 = u*u, u4 = u2*u2, u8 = u4*u4, u16 = u8*u8;
    return u16*u16*u2*u;
}
__device__ __forceinline__ float silu(float v) {
    return v / (1.0f + expf(-v));
}

// scalar fast h = 0.5 + (1/pi) atan(100 d)
__device__ __forceinline__ float fast_h(float d) {
    float x  = d * 100.0f;
    float ax = fabsf(x);
    float inv;
    asm("rcp.approx.f32 %0, %1;" : "=f"(inv) : "f"(ax));
    bool  big = ax > 1.0f;
    float t = big ? inv : ax;
    float s = t * t;
    float p =          -0.01172120f;
    p = fmaf(p, s,  0.05265332f);
    p = fmaf(p, s, -0.11643287f);
    p = fmaf(p, s,  0.19354346f);
    p = fmaf(p, s, -0.33262347f);
    p = fmaf(p, s,  0.99997726f);
    float r = t * p;
    r = big ? (1.5707963267948966f - r) : r;
    r = (x < 0.0f) ? -r : r;
    return fmaf(INV_PI_F, r, 0.5f);
}

struct Cand {
    float s1,c1,s2,c2,s3,c3,s4,c4;
    float sg13, sg42, off13, off42;
    float x0, y0;
};

__device__ __forceinline__ Cand make_cand(const float cp[5]) {
    Cand K;
    K.x0 = cp[3]; K.y0 = cp[4];
    float m0 = mod2pi(cp[0]), m1 = mod2pi(cp[1]), m2 = mod2pi(cp[2]);
    float lo = fminf(m0, m1), hi = fmaxf(m0, m1);
    float a1 = fminf(lo, m2);
    float a3 = fmaxf(hi, m2);
    float a2 = fmaxf(lo, fminf(hi, m2));
    float hm = mod2pi(0.5f*(a1 - a3));
    float a4 = 0.5f*(a1 + a3) + ((hm >= PI_F) ? PI_F : 0.0f);
    float d13 = mod2pi(a3 - a1);
    float d42 = mod2pi(a2 - a4);
    K.sg13 = (d13 < PI_F) ? 1.0f : -1.0f;
    K.sg42 = (d42 < PI_F) ? 1.0f : -1.0f;
    K.off13 = 0.1f * pow35(d13 / PI_F - 1.0f);
    K.off42 = 0.1f * pow35(d42 / PI_F - 1.0f);
    sincosf(a1, &K.s1, &K.c1);
    sincosf(a2, &K.s2, &K.c2);
    sincosf(a3, &K.s3, &K.c3);
    sincosf(a4, &K.s4, &K.c4);
    return K;
}

__device__ __forceinline__ void dists_at(const Cand& K, float dx, float t1, float t2,
                                         float t3, float t4, float& d13v, float& d42v) {
    float l1 = fmaf(-K.s1, dx, t1);
    float l2 = fmaf(-K.s2, dx, t2);
    float l3 = fmaf(-K.s3, dx, t3);
    float l4 = fmaf(-K.s4, dx, t4);
    d13v = fmaf(K.sg13, fminf(K.sg13*l1, -K.sg13*l3), K.off13);
    d42v = fmaf(K.sg42, fminf(K.sg42*l4, -K.sg42*l2), K.off42);
}

__device__ __forceinline__ float cand_range(int ip, int q) {
    return (ip < 3) ? (float)q * (TWO_PI_F / 31.0f)
                    : (-3.0f + (float)q * 0.2f);
}

// ---------------- kernels ----------------
__global__ void k_zero() {
    int t = blockIdx.x * blockDim.x + threadIdx.x;
    int stride = gridDim.x * blockDim.x;
    if (t < 16) g_stats[t] = 0.0f;
    for (int i = t; i < NBATCH*5*NPP;  i += stride) g_params[i]   = 0.0f;
    for (int i = t; i < NBATCH*3*NPIX; i += stride) g_smoothed[i] = 0.0f;
    for (int i = t; i < NBATCH*NPIX;   i += stride) g_gb[i]       = 0.0f;
}

__global__ void k_conv(const float* __restrict__ x, const float* __restrict__ rw) {
    int bo = blockIdx.x >> 4;
    int chunk = blockIdx.x & 15;
    int b = bo / 3, o = bo % 3;
    int pix = chunk * 256 + threadIdx.x;
    const float* xp = x + (size_t)b * CINN * NPIX + pix;
    float acc = 0.0f;
    #pragma unroll
    for (int c = 0; c < CINN; c++)
        acc = fmaf(xp[c * NPIX], rw[o * CINN + c], acc);
    g_y[(b*3 + o) * NPIX + pix] = acc;

    __shared__ float s1[256], s2[256];
    s1[threadIdx.x] = acc; s2[threadIdx.x] = acc * acc;
    __syncthreads();
    for (int s = 128; s > 0; s >>= 1) {
        if (threadIdx.x < s) { s1[threadIdx.x] += s1[threadIdx.x+s]; s2[threadIdx.x] += s2[threadIdx.x+s]; }
        __syncthreads();
    }
    if (threadIdx.x == 0) {
        atomicAdd(&g_stats[o],     s1[0]);
        atomicAdd(&g_stats[3 + o], s2[0]);
    }
}

__global__ void k_bnsilu(const float* __restrict__ gamma, const float* __restrict__ beta) {
    int t = blockIdx.x * 256 + threadIdx.x;
    int b = t >> 12, pix = t & (NPIX - 1);
    float v[3];
    #pragma unroll
    for (int c = 0; c < 3; c++) {
        float m   = g_stats[c]     * (1.0f / NSTAT);
        float var = g_stats[3 + c] * (1.0f / NSTAT) - m * m;
        float y   = g_y[(b*3 + c) * NPIX + pix];
        float n   = gamma[c] * (y - m) * rsqrtf(var + 1e-5f) + beta[c];
        v[c] = silu(n);
    }
    g_xr4[t] = make_float4(v[0], v[1], v[2], 0.0f);
}

// per-patch channel sums: one thread per (patch, row), shfl-reduce width 8
__global__ void k_psum() {
    int gt = blockIdx.x * 256 + threadIdx.x;
    int P  = gt >> 3, xr = gt & 7;
    float s0 = 0.0f, s1 = 0.0f, s2 = 0.0f;
    if (P < NPTOT) {
        int b = P / NPP, pp = P - b * NPP;
        int hp = pp / HPN, wp = pp - hp * HPN;
        const float4* row = g_xr4 + b * NPIX + (hp + xr) * WW + wp;
        #pragma unroll
        for (int yc = 0; yc < PSZ; yc++) {
            float4 v = __ldg(row + yc);
            s0 += v.x; s1 += v.y; s2 += v.z;
        }
    }
    #pragma unroll
    for (int off = 4; off > 0; off >>= 1) {
        s0 += __shfl_down_sync(0xffffffffu, s0, off, 8);
        s1 += __shfl_down_sync(0xffffffffu, s1, off, 8);
        s2 += __shfl_down_sync(0xffffffffu, s2, off, 8);
    }
    if (xr == 0 && P < NPTOT) g_ps4[P] = make_float4(s0, s1, s2, 0.0f);
}

// packed atan-based h for two candidate lanes
__device__ __forceinline__ f2 fast_h2(f2 d, f2 C100, f2 P5, f2 P4, f2 P3, f2 P2, f2 P1, f2 P0,
                                      f2 CIP, f2 CH) {
    f2 x = mul2(d, C100);
    float xa, xb; upk(x, xa, xb);
    float axa = fabsf(xa), axb = fabsf(xb);
    float ia, ib;
    asm("rcp.approx.f32 %0, %1;" : "=f"(ia) : "f"(axa));
    asm("rcp.approx.f32 %0, %1;" : "=f"(ib) : "f"(axb));
    bool biga = axa > 1.0f, bigb = axb > 1.0f;
    float ta = biga ? ia : axa;
    float tb = bigb ? ib : axb;
    f2 t = pk(ta, tb);
    f2 s = mul2(t, t);
    f2 p = P5;
    p = fma2(p, s, P4);
    p = fma2(p, s, P3);
    p = fma2(p, s, P2);
    p = fma2(p, s, P1);
    p = fma2(p, s, P0);
    f2 r = mul2(t, p);
    float ra, rb; upk(r, ra, rb);
    ra = biga ? (1.5707963267948966f - ra) : ra;
    rb = bigb ? (1.5707963267948966f - rb) : rb;
    ra = (xa < 0.0f) ? -ra : ra;
    rb = (xb < 0.0f) ? -rb : rb;
    return fma2(pk(ra, rb), CIP, CH);
}

// 8 patches x 16 threads; each thread evaluates candidates (2t, 2t+1) packed in f32x2 lanes
__global__ void __launch_bounds__(128) k_step(int ip) {
    int tid = threadIdx.x;
    int lp = tid >> 4;            // patch within block
    int tq = tid & 15;            // candidate-pair index
    int qa = 2 * tq;
    int qb = (2 * tq + 1 < NV) ? (2 * tq + 1) : (NV - 1);
    int P = blockIdx.x * 8 + lp;
    __shared__ float sLoss[8 * NV];

    bool valid = (P < NPTOT);
    int b = 0, pp = 0;
    float pbase = 0.0f;
    float scoreA = 3.4e38f, scoreB = 3.4e38f;

    if (valid) {
        b = P / NPP; pp = P - b * NPP;
        int hp = pp / HPN, wp = pp - hp * HPN;
        float p[5];
        #pragma unroll
        for (int j = 0; j < 5; j++) p[j] = g_params[(b*5 + j) * NPP + pp];
        pbase = p[ip];

        float cpA[5], cpB[5];
        #pragma unroll
        for (int j = 0; j < 5; j++) { cpA[j] = p[j]; cpB[j] = p[j]; }
        cpA[ip] += cand_range(ip, qa);
        cpB[ip] += cand_range(ip, qb);

        Cand A = make_cand(cpA);
        Cand B = make_cand(cpB);

        // packed candidate constants
        f2 ns1 = pk(-A.s1, -B.s1), ns2 = pk(-A.s2, -B.s2);
        f2 ns3 = pk(-A.s3, -B.s3), ns4 = pk(-A.s4, -B.s4);
        f2 c1 = pk(A.c1, B.c1), c2 = pk(A.c2, B.c2);
        f2 c3 = pk(A.c3, B.c3), c4 = pk(A.c4, B.c4);
        f2 sg13  = pk(A.sg13, B.sg13),  sg42  = pk(A.sg42, B.sg42);
        f2 nsg13 = pk(-A.sg13, -B.sg13), nsg42 = pk(-A.sg42, -B.sg42);
        f2 off13 = pk(A.off13, B.off13), off42 = pk(A.off42, B.off42);

        // constants (hoisted packed literals)
        f2 C100 = pk(100.0f, 100.0f);
        f2 P5c = pk(-0.01172120f, -0.01172120f);
        f2 P4c = pk( 0.05265332f,  0.05265332f);
        f2 P3c = pk(-0.11643287f, -0.11643287f);
        f2 P2c = pk( 0.19354346f,  0.19354346f);
        f2 P1c = pk(-0.33262347f, -0.33262347f);
        f2 P0c = pk( 0.99997726f,  0.99997726f);
        f2 CIP = pk(INV_PI_F, INV_PI_F);
        f2 CH  = pk(0.5f, 0.5f);
        f2 CN1 = pk(-1.0f, -1.0f);
        f2 C1  = pk(1.0f, 1.0f);

        f2 dxv[PSZ];
        #pragma unroll
        for (int yc = 0; yc < PSZ; yc++) {
            float cc = -1.0f + (float)yc * (2.0f/7.0f);
            dxv[yc] = pk(cc - A.x0, cc - B.x0);
        }

        const float4* tile = g_xr4 + b * NPIX + hp * WW + wp;
        float4 S = __ldg(&g_ps4[P]);

        // packed accumulators (lanes = candidates)
        f2 sw0 = 0, sw1 = 0;
        f2 cn00 = 0, cn01 = 0, cn10 = 0, cn11 = 0, cn20 = 0, cn21 = 0;
        f2 G00 = 0, G11 = 0, G01 = 0;

        #pragma unroll 1
        for (int xr = 0; xr < PSZ; xr++) {
            float rc = -1.0f + (float)xr * (2.0f/7.0f);
            f2 dy = pk(rc - A.y0, rc - B.y0);
            f2 t1 = mul2(c1, dy), t2 = mul2(c2, dy), t3 = mul2(c3, dy), t4 = mul2(c4, dy);
            const float4* row = tile + xr * WW;
            #pragma unroll
            for (int yc = 0; yc < PSZ; yc++) {
                f2 dx = dxv[yc];
                f2 l1 = fma2(ns1, dx, t1);
                f2 l2 = fma2(ns2, dx, t2);
                f2 l3 = fma2(ns3, dx, t3);
                f2 l4 = fma2(ns4, dx, t4);
                // d13 = sg13*min(sg13*l1, -sg13*l3) + off13
                f2 u = mul2(sg13, l1), v = mul2(nsg13, l3);
                float ua, ub, va, vb; upk(u, ua, ub); upk(v, va, vb);
                f2 m13 = pk(fminf(ua, va), fminf(ub, vb));
                f2 d13 = fma2(sg13, m13, off13);
                u = mul2(sg42, l4); v = mul2(nsg42, l2);
                upk(u, ua, ub); upk(v, va, vb);
                f2 m42 = pk(fminf(ua, va), fminf(ub, vb));
                f2 d42 = fma2(sg42, m42, off42);

                f2 h0 = fast_h2(d13, C100, P5c, P4c, P3c, P2c, P1c, P0c, CIP, CH);
                f2 h1 = fast_h2(d42, C100, P5c, P4c, P3c, P2c, P1c, P0c, CIP, CH);
                f2 w0 = fma2(h0, CN1, C1);          // 1 - h0
                f2 hh = mul2(h0, h1);
                f2 w1 = fma2(hh, CN1, h0);          // h0 - h0*h1

                float4 img = __ldg(row + yc);
                f2 ix = pk(img.x, img.x), iy = pk(img.y, img.y), iz = pk(img.z, img.z);
                sw0 = add2(sw0, w0); sw1 = add2(sw1, w1);
                cn00 = fma2(ix, w0, cn00); cn01 = fma2(ix, w1, cn01);
                cn10 = fma2(iy, w0, cn10); cn11 = fma2(iy, w1, cn11);
                cn20 = fma2(iz, w0, cn20); cn21 = fma2(iz, w1, cn21);
                G00 = fma2(w0, w0, G00); G11 = fma2(w1, w1, G11); G01 = fma2(w0, w1, G01);
            }
        }

        // unpack and score each lane
        float sw0a, sw0b, sw1a, sw1b;
        upk(sw0, sw0a, sw0b); upk(sw1, sw1a, sw1b);
        float n00a,n00b,n01a,n01b,n10a,n10b,n11a,n11b,n20a,n20b,n21a,n21b;
        upk(cn00,n00a,n00b); upk(cn01,n01a,n01b);
        upk(cn10,n10a,n10b); upk(cn11,n11a,n11b);
        upk(cn20,n20a,n20b); upk(cn21,n21a,n21b);
        float g00a,g00b,g11a,g11b,g01a,g01b;
        upk(G00,g00a,g00b); upk(G11,g11a,g11b); upk(G01,g01a,g01b);
        float Sc[3] = {S.x, S.y, S.z};

        #pragma unroll
        for (int lane = 0; lane < 2; lane++) {
            float s0 = lane ? sw0b : sw0a;
            float s1 = lane ? sw1b : sw1a;
            float q00 = lane ? g00b : g00a;
            float q11 = lane ? g11b : g11a;
            float q01 = lane ? g01b : g01a;
            float n0a_[3] = { lane?n00b:n00a, lane?n10b:n10a, lane?n20b:n20a };
            float n1a_[3] = { lane?n01b:n01a, lane?n11b:n11a, lane?n21b:n21a };
            float s2 = 64.0f - s0 - s1;
            float q02 = s0 - q00 - q01;
            float q12 = s1 - q01 - q11;
            float q22 = s2 - q02 - q12;
            float i0 = 1.0f / (s0 + 1e-10f);
            float i1 = 1.0f / (s1 + 1e-10f);
            float i2 = 1.0f / (s2 + 1e-10f);
            float sc = 0.0f;
            #pragma unroll
            for (int c = 0; c < 3; c++) {
                float n0 = n0a_[c], n1 = n1a_[c];
                float n2 = Sc[c] - n0 - n1;
                float c0 = n0*i0, c1_ = n1*i1, c2_ = n2*i2;
                float quad = c0*c0*q00 + c1_*c1_*q11 + c2_*c2_*q22
                           + 2.0f*(c0*c1_*q01 + c0*c2_*q02 + c1_*c2_*q12);
                sc += quad - 2.0f*(c0*n0 + c1_*n1 + c2_*n2);
            }
            if (lane == 0) scoreA = sc; else scoreB = sc;
        }
    }

    if (valid) {
        sLoss[lp * NV + qa] = scoreA;
        if (2 * tq + 1 < NV) sLoss[lp * NV + qb] = scoreB;
    }
    __syncthreads();

    if (valid && tq == 0) {
        int best = 0;
        float bl = sLoss[lp * NV];
        #pragma unroll
        for (int k = 1; k < NV; k++) {
            float v = sLoss[lp * NV + k];
            if (v < bl) { bl = v; best = k; }
        }
        g_params[(b*5 + ip) * NPP + pp] = pbase + cand_range(ip, best);
    }
}

__global__ void k_final() {
    int P = blockIdx.x * blockDim.x + threadIdx.x;
    if (P >= NPTOT) return;
    int b = P / NPP, pp = P - b * NPP;
    int hp = pp / HPN, wp = pp - hp * HPN;

    float cp[5];
    #pragma unroll
    for (int j = 0; j < 5; j++) cp[j] = g_params[(b*5 + j) * NPP + pp];
    Cand K = make_cand(cp);
    const float4* tile = g_xr4 + b * NPIX + hp * WW + wp;

    float dxv[PSZ];
    #pragma unroll
    for (int yc = 0; yc < PSZ; yc++)
        dxv[yc] = (-1.0f + (float)yc * (2.0f/7.0f)) - K.x0;

    float sw[3] = {0,0,0};
    float cn[3][3] = {{0,0,0},{0,0,0},{0,0,0}};
    #pragma unroll 1
    for (int xr = 0; xr < PSZ; xr++) {
        float dy = (-1.0f + (float)xr * (2.0f/7.0f)) - K.y0;
        float t1 = K.c1*dy, t2 = K.c2*dy, t3 = K.c3*dy, t4 = K.c4*dy;
        const float4* row = tile + xr * WW;
        #pragma unroll
        for (int yc = 0; yc < PSZ; yc++) {
            float d13v, d42v;
            dists_at(K, dxv[yc], t1, t2, t3, t4, d13v, d42v);
            float h0 = fast_h(d13v);
            float h1 = fast_h(d42v);
            float w0 = 1.0f - h0, w1 = h0 * (1.0f - h1), w2 = h0 * h1;
            float4 img = __ldg(row + yc);
            sw[0] += w0; sw[1] += w1; sw[2] += w2;
            cn[0][0] = fmaf(img.x,w0,cn[0][0]); cn[0][1] = fmaf(img.x,w1,cn[0][1]); cn[0][2] = fmaf(img.x,w2,cn[0][2]);
            cn[1][0] = fmaf(img.y,w0,cn[1][0]); cn[1][1] = fmaf(img.y,w1,cn[1][1]); cn[1][2] = fmaf(img.y,w2,cn[1][2]);
            cn[2][0] = fmaf(img.z,w0,cn[2][0]); cn[2][1] = fmaf(img.z,w1,cn[2][1]); cn[2][2] = fmaf(img.z,w2,cn[2][2]);
        }
    }
    float col[3][3];
    #pragma unroll
    for (int k = 0; k < 3; k++) {
        float inv = 1.0f / (sw[k] + 1e-10f);
        col[0][k] = cn[0][k] * inv;
        col[1][k] = cn[1][k] * inv;
        col[2][k] = cn[2][k] * inv;
    }

    #pragma unroll 1
    for (int xr = 0; xr < PSZ; xr++) {
        float dy = (-1.0f + (float)xr * (2.0f/7.0f)) - K.y0;
        float t1 = K.c1*dy, t2 = K.c2*dy, t3 = K.c3*dy, t4 = K.c4*dy;
        int hh = xr + hp;
        #pragma unroll
        for (int yc = 0; yc < PSZ; yc++) {
            float d13v, d42v;
            dists_at(K, dxv[yc], t1, t2, t3, t4, d13v, d42v);
            float h0 = fast_h(d13v);
            float h1 = fast_h(d42v);
            float w0 = 1.0f - h0, w1 = h0 * (1.0f - h1), w2 = h0 * h1;
            int opix = hh * WW + yc + wp;
            #pragma unroll
            for (int c = 0; c < 3; c++) {
                float pv = w0*col[c][0] + w1*col[c][1] + w2*col[c][2];
                atomicAdd(&g_smoothed[(b*3 + c) * NPIX + opix], pv);
            }
            float d1 = d13v, d2 = d42v;
            float mad = (d1 < 0.0f) ? -d1
                      : ((d2 < 0.0f) ? fminf(d1, -d2) : fminf(d1, d2));
            float r = mad * 20.0f;
            float lb = 1.0f / (1.0f + r * r);
            atomicAdd(&g_gb[b * NPIX + opix], lb);
        }
    }
}

__global__ void k_post1(const float* __restrict__ fbw, const float* __restrict__ fiw) {
    int t = blockIdx.x * 256 + threadIdx.x;
    int b = t >> 12, pix = t & (NPIX - 1);
    int h = pix >> 6, w = pix & 63;
    int ch = min(min(h + 1, HH - h), PSZ);
    int cw = min(min(w + 1, WW - w), PSZ);
    float inv = 1.0f / (float)(ch * cw);

    float sm0 = g_smoothed[(b*3 + 0) * NPIX + pix] * inv;
    float sm1 = g_smoothed[(b*3 + 1) * NPIX + pix] * inv;
    float sm2 = g_smoothed[(b*3 + 2) * NPIX + pix] * inv;
    float yi = sm0 * fiw[0] + sm1 * fiw[1] + sm2 * fiw[2];
    float gbv = g_gb[t] * inv;
    float yb = gbv * fbw[0] + gbv * fbw[1] + gbv * fbw[2];
    g_yi[t] = yi;
    g_yb[t] = yb;

    __shared__ float sA[256], sB[256];
    sA[threadIdx.x] = yb; sB[threadIdx.x] = yb * yb;
    __syncthreads();
    for (int s = 128; s > 0; s >>= 1) {
        if (threadIdx.x < s) { sA[threadIdx.x] += sA[threadIdx.x+s]; sB[threadIdx.x] += sB[threadIdx.x+s]; }
        __syncthreads();
    }
    if (threadIdx.x == 0) { atomicAdd(&g_stats[6], sA[0]); atomicAdd(&g_stats[7], sB[0]); }
    __syncthreads();
    sA[threadIdx.x] = yi; sB[threadIdx.x] = yi * yi;
    __syncthreads();
    for (int s = 128; s > 0; s >>= 1) {
        if (threadIdx.x < s) { sA[threadIdx.x] += sA[threadIdx.x+s]; sB[threadIdx.x] += sB[threadIdx.x+s]; }
        __syncthreads();
    }
    if (threadIdx.x == 0) { atomicAdd(&g_stats[8], sA[0]); atomicAdd(&g_stats[9], sB[0]); }
}

__global__ void k_out(float* __restrict__ out,
                      const float* __restrict__ fbg, const float* __restrict__ fbb,
                      const float* __restrict__ fig, const float* __restrict__ fib) {
    int t = blockIdx.x * 256 + threadIdx.x;
    float mb = g_stats[6] * (1.0f / NSTAT);
    float vb = g_stats[7] * (1.0f / NSTAT) - mb * mb;
    float nb = fbg[0] * (g_yb[t] - mb) * rsqrtf(vb + 1e-5f) + fbb[0];
    out[t] = silu(nb);

    float mi = g_stats[8] * (1.0f / NSTAT);
    float vi = g_stats[9] * (1.0f / NSTAT) - mi * mi;
    float ni = fig[0] * (g_yi[t] - mi) * rsqrtf(vi + 1e-5f) + fib[0];
    out[NBATCH * NPIX + t] = silu(ni);
}

// ---------------- launch ----------------
extern "C" void kernel_launch(void* const* d_in, const int* in_sizes, int n_in,
                              void* d_out, int out_size) {
    const float* x   = (const float*)d_in[0];
    const float* rw  = (const float*)d_in[1];
    const float* rg  = (const float*)d_in[2];
    const float* rb  = (const float*)d_in[3];
    const float* fbw = (const float*)d_in[4];
    const float* fbg = (const float*)d_in[5];
    const float* fbb = (const float*)d_in[6];
    const float* fiw = (const float*)d_in[7];
    const float* fig = (const float*)d_in[8];
    const float* fib = (const float*)d_in[9];
    float* out = (float*)d_out;

    k_zero<<<64, 256>>>();
    k_conv<<<NBATCH * 3 * 16, 256>>>(x, rw);
    k_bnsilu<<<32, 256>>>(rg, rb);
    k_psum<<<(NPTOT * 8 + 255) / 256, 256>>>();
    for (int i = 0; i < 5; i++)
        k_step<<<(NPTOT + 7) / 8, 128>>>(i);
    k_final<<<(NPTOT + 255) / 256, 256>>>();
    k_post1<<<32, 256>>>(fbw, fiw);
    k_out<<<32, 256>>>(out, fbg, fbb, fig, fib);
}

// round 4
// speedup vs baseline: 1.1375x; 1.1375x over previous
#include <cuda_runtime.h>
#include <math.h>

#define TWO_PI_F 6.28318530717958647692f
#define PI_F     3.14159265358979323846f
#define INV_PI_F 0.31830988618367094f

#define PSZ   8
#define HH    64
#define WW    64
#define HPN   57
#define NPP   (HPN*HPN)        // 3249
#define NBATCH 2
#define NPTOT (NBATCH*NPP)     // 6498
#define NV    31
#define CINN  32
#define NPIX  (HH*WW)          // 4096
#define NSTAT 8192

// ---------------- device scratch ----------------
__device__ float  g_y[NBATCH*3*NPIX];
__device__ float4 g_xr4[NBATCH*NPIX];
__device__ float4 g_ps4[NPTOT];
__device__ float  g_params[NBATCH*5*NPP];
__device__ float  g_smoothed[NBATCH*3*NPIX];
__device__ float  g_gb[NBATCH*NPIX];
__device__ float  g_yb[NBATCH*NPIX];
__device__ float  g_yi[NBATCH*NPIX];
__device__ float  g_stats[16];

// ---------------- helpers ----------------
__device__ __forceinline__ float mod2pi(float v) {
    float m = fmodf(v, TWO_PI_F);
    return (m < 0.0f) ? m + TWO_PI_F : m;
}
__device__ __forceinline__ float pow35(float u) {
    float u2 = u*u, u4 = u2*u2, u8 = u4*u4, u16 = u8*u8;
    return u16*u16*u2*u;
}
__device__ __forceinline__ float silu(float v) {
    return v / (1.0f + expf(-v));
}

// h = 0.5 + (1/pi) * atan(x), x pre-scaled by 1/eta (=100)
// deg-9 odd minimax on [0,1] + reciprocal range reduction, err(h) ~ 3e-6
__device__ __forceinline__ float fast_hs(float x) {
    float ax = fabsf(x);
    float inv;
    asm("rcp.approx.f32 %0, %1;" : "=f"(inv) : "f"(ax));
    bool  big = ax > 1.0f;
    float t = big ? inv : ax;
    float s = t * t;
    float p =           0.0208351f;
    p = fmaf(p, s, -0.0851330f);
    p = fmaf(p, s,  0.1801410f);
    p = fmaf(p, s, -0.3302995f);
    p = fmaf(p, s,  0.9998660f);
    float r = t * p;
    r = big ? (1.5707963267948966f - r) : r;
    r = (x < 0.0f) ? -r : r;
    return fmaf(INV_PI_F, r, 0.5f);
}

// Candidate with sign- and 1/eta- folded line coefficients.
// l1' = A1x*dx + A1y*dy  ==  100*sg13*line(a1)
// l3''= A3x*dx + A3y*dy  == -100*sg13*line(a3)
// d13s = sg13*min(l1', l3'') + off13s   (== 100 * d13)
struct Cand {
    float A1x,A1y,A3x,A3y,A4x,A4y,A2x,A2y;
    float sg13, sg42, off13s, off42s;
    float x0, y0;
};

__device__ __forceinline__ Cand make_cand(const float cp[5]) {
    Cand K;
    K.x0 = cp[3]; K.y0 = cp[4];
    float m0 = mod2pi(cp[0]), m1 = mod2pi(cp[1]), m2 = mod2pi(cp[2]);
    float lo = fminf(m0, m1), hi = fmaxf(m0, m1);
    float a1 = fminf(lo, m2);
    float a3 = fmaxf(hi, m2);
    float a2 = fmaxf(lo, fminf(hi, m2));
    float hm = mod2pi(0.5f*(a1 - a3));
    float a4 = 0.5f*(a1 + a3) + ((hm >= PI_F) ? PI_F : 0.0f);
    float d13 = mod2pi(a3 - a1);
    float d42 = mod2pi(a2 - a4);
    K.sg13 = (d13 < PI_F) ? 1.0f : -1.0f;
    K.sg42 = (d42 < PI_F) ? 1.0f : -1.0f;
    K.off13s = 10.0f * pow35(d13 / PI_F - 1.0f);   // 100 * 0.1 * g
    K.off42s = 10.0f * pow35(d42 / PI_F - 1.0f);
    float s1,c1,s2,c2,s3,c3,s4,c4;
    sincosf(a1, &s1, &c1);
    sincosf(a2, &s2, &c2);
    sincosf(a3, &s3, &c3);
    sincosf(a4, &s4, &c4);
    float f13 = 100.0f * K.sg13, f42 = 100.0f * K.sg42;
    K.A1x = -f13 * s1;  K.A1y =  f13 * c1;
    K.A3x =  f13 * s3;  K.A3y = -f13 * c3;
    K.A4x = -f42 * s4;  K.A4y =  f42 * c4;
    K.A2x =  f42 * s2;  K.A2y = -f42 * c2;
    return K;
}

// scaled dists: d13s = 100*d13, d42s = 100*d42
__device__ __forceinline__ void dists_scaled(const Cand& K, float dx,
                                             float T1, float T3, float T4, float T2,
                                             float& d13s, float& d42s) {
    float l1 = fmaf(K.A1x, dx, T1);
    float l3 = fmaf(K.A3x, dx, T3);
    float l4 = fmaf(K.A4x, dx, T4);
    float l2 = fmaf(K.A2x, dx, T2);
    d13s = fmaf(K.sg13, fminf(l1, l3), K.off13s);
    d42s = fmaf(K.sg42, fminf(l4, l2), K.off42s);
}

__device__ __forceinline__ float cand_range(int ip, int q) {
    return (ip < 3) ? (float)q * (TWO_PI_F / 31.0f)
                    : (-3.0f + (float)q * 0.2f);
}

// ---------------- kernels ----------------
__global__ void k_zero() {
    int t = blockIdx.x * blockDim.x + threadIdx.x;
    int stride = gridDim.x * blockDim.x;
    if (t < 16) g_stats[t] = 0.0f;
    for (int i = t; i < NBATCH*5*NPP;  i += stride) g_params[i]   = 0.0f;
    for (int i = t; i < NBATCH*3*NPIX; i += stride) g_smoothed[i] = 0.0f;
    for (int i = t; i < NBATCH*NPIX;   i += stride) g_gb[i]       = 0.0f;
}

__global__ void k_conv(const float* __restrict__ x, const float* __restrict__ rw) {
    int bo = blockIdx.x >> 4;
    int chunk = blockIdx.x & 15;
    int b = bo / 3, o = bo % 3;
    int pix = chunk * 256 + threadIdx.x;
    const float* xp = x + (size_t)b * CINN * NPIX + pix;
    float acc = 0.0f;
    #pragma unroll
    for (int c = 0; c < CINN; c++)
        acc = fmaf(xp[c * NPIX], rw[o * CINN + c], acc);
    g_y[(b*3 + o) * NPIX + pix] = acc;

    __shared__ float s1[256], s2[256];
    s1[threadIdx.x] = acc; s2[threadIdx.x] = acc * acc;
    __syncthreads();
    for (int s = 128; s > 0; s >>= 1) {
        if (threadIdx.x < s) { s1[threadIdx.x] += s1[threadIdx.x+s]; s2[threadIdx.x] += s2[threadIdx.x+s]; }
        __syncthreads();
    }
    if (threadIdx.x == 0) {
        atomicAdd(&g_stats[o],     s1[0]);
        atomicAdd(&g_stats[3 + o], s2[0]);
    }
}

__global__ void k_bnsilu(const float* __restrict__ gamma, const float* __restrict__ beta) {
    int t = blockIdx.x * 256 + threadIdx.x;
    int b = t >> 12, pix = t & (NPIX - 1);
    float v[3];
    #pragma unroll
    for (int c = 0; c < 3; c++) {
        float m   = g_stats[c]     * (1.0f / NSTAT);
        float var = g_stats[3 + c] * (1.0f / NSTAT) - m * m;
        float y   = g_y[(b*3 + c) * NPIX + pix];
        float n   = gamma[c] * (y - m) * rsqrtf(var + 1e-5f) + beta[c];
        v[c] = silu(n);
    }
    g_xr4[t] = make_float4(v[0], v[1], v[2], 0.0f);
}

// per-patch channel sums: one thread per (patch, row), shfl-reduce width 8
__global__ void k_psum() {
    int gt = blockIdx.x * 256 + threadIdx.x;
    int P  = gt >> 3, xr = gt & 7;
    float s0 = 0.0f, s1 = 0.0f, s2 = 0.0f;
    if (P < NPTOT) {
        int b = P / NPP, pp = P - b * NPP;
        int hp = pp / HPN, wp = pp - hp * HPN;
        const float4* row = g_xr4 + b * NPIX + (hp + xr) * WW + wp;
        #pragma unroll
        for (int yc = 0; yc < PSZ; yc++) {
            float4 v = __ldg(row + yc);
            s0 += v.x; s1 += v.y; s2 += v.z;
        }
    }
    #pragma unroll
    for (int off = 4; off > 0; off >>= 1) {
        s0 += __shfl_down_sync(0xffffffffu, s0, off, 8);
        s1 += __shfl_down_sync(0xffffffffu, s1, off, 8);
        s2 += __shfl_down_sync(0xffffffffu, s2, off, 8);
    }
    if (xr == 0 && P < NPTOT) g_ps4[P] = make_float4(s0, s1, s2, 0.0f);
}

__global__ void __launch_bounds__(248) k_step(int ip) {
    int tid = threadIdx.x;
    int lp = tid / NV, q = tid - lp * NV;
    int P = blockIdx.x * 8 + lp;
    __shared__ float sLoss[248];

    bool valid = (P < NPTOT);
    int b = 0, pp = 0;
    float p[5] = {0,0,0,0,0};
    float score = 3.4e38f;

    if (valid) {
        b = P / NPP; pp = P - b * NPP;
        int hp = pp / HPN, wp = pp - hp * HPN;
        #pragma unroll
        for (int j = 0; j < 5; j++) p[j] = g_params[(b*5 + j) * NPP + pp];

        float cp[5];
        #pragma unroll
        for (int j = 0; j < 5; j++) cp[j] = p[j];
        cp[ip] += cand_range(ip, q);

        Cand K = make_cand(cp);
        const float4* tile = g_xr4 + b * NPIX + hp * WW + wp;
        float4 S = __ldg(&g_ps4[P]);

        float dxv[PSZ];
        #pragma unroll
        for (int yc = 0; yc < PSZ; yc++)
            dxv[yc] = (-1.0f + (float)yc * (2.0f/7.0f)) - K.x0;

        float sw0=0.f, sw1=0.f;
        float cn00=0.f,cn01=0.f, cn10=0.f,cn11=0.f, cn20=0.f,cn21=0.f;
        float G00=0.f,G11=0.f,G01=0.f;

        #pragma unroll 1
        for (int xr = 0; xr < PSZ; xr++) {
            float dy = (-1.0f + (float)xr * (2.0f/7.0f)) - K.y0;
            float T1 = K.A1y*dy, T3 = K.A3y*dy, T4 = K.A4y*dy, T2 = K.A2y*dy;
            const float4* row = tile + xr * WW;
            #pragma unroll
            for (int yc = 0; yc < PSZ; yc++) {
                float d13s, d42s;
                dists_scaled(K, dxv[yc], T1, T3, T4, T2, d13s, d42s);
                float h0 = fast_hs(d13s);
                float h1 = fast_hs(d42s);
                float w0 = 1.0f - h0;
                float w1 = h0 * (1.0f - h1);
                float4 img = __ldg(row + yc);
                sw0 += w0; sw1 += w1;
                cn00 = fmaf(img.x, w0, cn00); cn01 = fmaf(img.x, w1, cn01);
                cn10 = fmaf(img.y, w0, cn10); cn11 = fmaf(img.y, w1, cn11);
                cn20 = fmaf(img.z, w0, cn20); cn21 = fmaf(img.z, w1, cn21);
                G00 = fmaf(w0, w0, G00); G11 = fmaf(w1, w1, G11); G01 = fmaf(w0, w1, G01);
            }
        }
        float sw2 = 64.0f - sw0 - sw1;
        float G02 = sw0 - G00 - G01;
        float G12 = sw1 - G01 - G11;
        float G22 = sw2 - G02 - G12;
        float i0 = 1.0f / (sw0 + 1e-10f);
        float i1 = 1.0f / (sw1 + 1e-10f);
        float i2 = 1.0f / (sw2 + 1e-10f);
        float Sc[3] = {S.x, S.y, S.z};
        float n0a[3] = {cn00, cn10, cn20};
        float n1a[3] = {cn01, cn11, cn21};
        score = 0.0f;
        #pragma unroll
        for (int c = 0; c < 3; c++) {
            float n0 = n0a[c], n1 = n1a[c];
            float n2 = Sc[c] - n0 - n1;
            float c0 = n0*i0, c1 = n1*i1, c2 = n2*i2;
            float quad = c0*c0*G00 + c1*c1*G11 + c2*c2*G22
                       + 2.0f*(c0*c1*G01 + c0*c2*G02 + c1*c2*G12);
            score += quad - 2.0f*(c0*n0 + c1*n1 + c2*n2);
        }
    }
    sLoss[tid] = score;
    __syncthreads();

    if (valid && q == 0) {
        int best = 0;
        float bl = sLoss[lp * NV];
        #pragma unroll
        for (int k = 1; k < NV; k++) {
            float v = sLoss[lp * NV + k];
            if (v < bl) { bl = v; best = k; }
        }
        g_params[(b*5 + ip) * NPP + pp] = p[ip] + cand_range(ip, best);
    }
}

__global__ void k_final() {
    int P = blockIdx.x * blockDim.x + threadIdx.x;
    if (P >= NPTOT) return;
    int b = P / NPP, pp = P - b * NPP;
    int hp = pp / HPN, wp = pp - hp * HPN;

    float cp[5];
    #pragma unroll
    for (int j = 0; j < 5; j++) cp[j] = g_params[(b*5 + j) * NPP + pp];
    Cand K = make_cand(cp);
    const float4* tile = g_xr4 + b * NPIX + hp * WW + wp;

    float dxv[PSZ];
    #pragma unroll
    for (int yc = 0; yc < PSZ; yc++)
        dxv[yc] = (-1.0f + (float)yc * (2.0f/7.0f)) - K.x0;

    float sw[3] = {0,0,0};
    float cn[3][3] = {{0,0,0},{0,0,0},{0,0,0}};
    #pragma unroll 1
    for (int xr = 0; xr < PSZ; xr++) {
        float dy = (-1.0f + (float)xr * (2.0f/7.0f)) - K.y0;
        float T1 = K.A1y*dy, T3 = K.A3y*dy, T4 = K.A4y*dy, T2 = K.A2y*dy;
        const float4* row = tile + xr * WW;
        #pragma unroll
        for (int yc = 0; yc < PSZ; yc++) {
            float d13s, d42s;
            dists_scaled(K, dxv[yc], T1, T3, T4, T2, d13s, d42s);
            float h0 = fast_hs(d13s);
            float h1 = fast_hs(d42s);
            float w0 = 1.0f - h0, w1 = h0 * (1.0f - h1), w2 = h0 * h1;
            float4 img = __ldg(row + yc);
            sw[0] += w0; sw[1] += w1; sw[2] += w2;
            cn[0][0] = fmaf(img.x,w0,cn[0][0]); cn[0][1] = fmaf(img.x,w1,cn[0][1]); cn[0][2] = fmaf(img.x,w2,cn[0][2]);
            cn[1][0] = fmaf(img.y,w0,cn[1][0]); cn[1][1] = fmaf(img.y,w1,cn[1][1]); cn[1][2] = fmaf(img.y,w2,cn[1][2]);
            cn[2][0] = fmaf(img.z,w0,cn[2][0]); cn[2][1] = fmaf(img.z,w1,cn[2][1]); cn[2][2] = fmaf(img.z,w2,cn[2][2]);
        }
    }
    float col[3][3];
    #pragma unroll
    for (int k = 0; k < 3; k++) {
        float inv = 1.0f / (sw[k] + 1e-10f);
        col[0][k] = cn[0][k] * inv;
        col[1][k] = cn[1][k] * inv;
        col[2][k] = cn[2][k] * inv;
    }

    #pragma unroll 1
    for (int xr = 0; xr < PSZ; xr++) {
        float dy = (-1.0f + (float)xr * (2.0f/7.0f)) - K.y0;
        float T1 = K.A1y*dy, T3 = K.A3y*dy, T4 = K.A4y*dy, T2 = K.A2y*dy;
        int hh = xr + hp;
        #pragma unroll
        for (int yc = 0; yc < PSZ; yc++) {
            float d13s, d42s;
            dists_scaled(K, dxv[yc], T1, T3, T4, T2, d13s, d42s);
            float h0 = fast_hs(d13s);
            float h1 = fast_hs(d42s);
            float w0 = 1.0f - h0, w1 = h0 * (1.0f - h1), w2 = h0 * h1;
            int opix = hh * WW + yc + wp;
            #pragma unroll
            for (int c = 0; c < 3; c++) {
                float pv = w0*col[c][0] + w1*col[c][1] + w2*col[c][2];
                atomicAdd(&g_smoothed[(b*3 + c) * NPIX + opix], pv);
            }
            // scaled dists: mad' = 100*mad; lb = 1/(1+(mad*20)^2) = 1/(1+(mad'*0.2)^2)
            float d1 = d13s, d2 = d42s;
            float mad = (d1 < 0.0f) ? -d1
                      : ((d2 < 0.0f) ? fminf(d1, -d2) : fminf(d1, d2));
            float r = mad * 0.2f;
            float lb = 1.0f / (1.0f + r * r);
            atomicAdd(&g_gb[b * NPIX + opix], lb);
        }
    }
}

__global__ void k_post1(const float* __restrict__ fbw, const float* __restrict__ fiw) {
    int t = blockIdx.x * 256 + threadIdx.x;
    int b = t >> 12, pix = t & (NPIX - 1);
    int h = pix >> 6, w = pix & 63;
    int ch = min(min(h + 1, HH - h), PSZ);
    int cw = min(min(w + 1, WW - w), PSZ);
    float inv = 1.0f / (float)(ch * cw);

    float sm0 = g_smoothed[(b*3 + 0) * NPIX + pix] * inv;
    float sm1 = g_smoothed[(b*3 + 1) * NPIX + pix] * inv;
    float sm2 = g_smoothed[(b*3 + 2) * NPIX + pix] * inv;
    float yi = sm0 * fiw[0] + sm1 * fiw[1] + sm2 * fiw[2];
    float gbv = g_gb[t] * inv;
    float yb = gbv * fbw[0] + gbv * fbw[1] + gbv * fbw[2];
    g_yi[t] = yi;
    g_yb[t] = yb;

    __shared__ float sA[256], sB[256];
    sA[threadIdx.x] = yb; sB[threadIdx.x] = yb * yb;
    __syncthreads();
    for (int s = 128; s > 0; s >>= 1) {
        if (threadIdx.x < s) { sA[threadIdx.x] += sA[threadIdx.x+s]; sB[threadIdx.x] += sB[threadIdx.x+s]; }
        __syncthreads();
    }
    if (threadIdx.x == 0) { atomicAdd(&g_stats[6], sA[0]); atomicAdd(&g_stats[7], sB[0]); }
    __syncthreads();
    sA[threadIdx.x] = yi; sB[threadIdx.x] = yi * yi;
    __syncthreads();
    for (int s = 128; s > 0; s >>= 1) {
        if (threadIdx.x < s) { sA[threadIdx.x] += sA[threadIdx.x+s]; sB[threadIdx.x] += sB[threadIdx.x+s]; }
        __syncthreads();
    }
    if (threadIdx.x == 0) { atomicAdd(&g_stats[8], sA[0]); atomicAdd(&g_stats[9], sB[0]); }
}

__global__ void k_out(float* __restrict__ out,
                      const float* __restrict__ fbg, const float* __restrict__ fbb,
                      const float* __restrict__ fig, const float* __restrict__ fib) {
    int t = blockIdx.x * 256 + threadIdx.x;
    float mb = g_stats[6] * (1.0f / NSTAT);
    float vb = g_stats[7] * (1.0f / NSTAT) - mb * mb;
    float nb = fbg[0] * (g_yb[t] - mb) * rsqrtf(vb + 1e-5f) + fbb[0];
    out[t] = silu(nb);

    float mi = g_stats[8] * (1.0f / NSTAT);
    float vi = g_stats[9] * (1.0f / NSTAT) - mi * mi;
    float ni = fig[0] * (g_yi[t] - mi) * rsqrtf(vi + 1e-5f) + fib[0];
    out[NBATCH * NPIX + t] = silu(ni);
}

// ---------------- launch ----------------
extern "C" void kernel_launch(void* const* d_in, const int* in_sizes, int n_in,
                              void* d_out, int out_size) {
    const float* x   = (const float*)d_in[0];
    const float* rw  = (const float*)d_in[1];
    const float* rg  = (const float*)d_in[2];
    const float* rb  = (const float*)d_in[3];
    const float* fbw = (const float*)d_in[4];
    const float* fbg = (const float*)d_in[5];
    const float* fbb = (const float*)d_in[6];
    const float* fiw = (const float*)d_in[7];
    const float* fig = (const float*)d_in[8];
    const float* fib = (const float*)d_in[9];
    float* out = (float*)d_out;

    k_zero<<<64, 256>>>();
    k_conv<<<NBATCH * 3 * 16, 256>>>(x, rw);
    k_bnsilu<<<32, 256>>>(rg, rb);
    k_psum<<<(NPTOT * 8 + 255) / 256, 256>>>();
    for (int i = 0; i < 5; i++)
        k_step<<<(NPTOT + 7) / 8, 248>>>(i);
    k_final<<<(NPTOT + 255) / 256, 256>>>();
    k_post1<<<32, 256>>>(fbw, fiw);
    k_out<<<32, 256>>>(out, fbg, fbb, fig, fib);
}

// round 5
// speedup vs baseline: 1.1681x; 1.0269x over previous
#include <cuda_runtime.h>
#include <math.h>

#define TWO_PI_F 6.28318530717958647692f
#define PI_F     3.14159265358979323846f
#define INV_PI_F 0.31830988618367094f

#define PSZ   8
#define HH    64
#define WW    64
#define HPN   57
#define NPP   (HPN*HPN)        // 3249
#define NBATCH 2
#define NPTOT (NBATCH*NPP)     // 6498
#define NV    31
#define CINN  32
#define NPIX  (HH*WW)          // 4096
#define NSTAT 8192

// ---------------- device scratch ----------------
__device__ float  g_y[NBATCH*3*NPIX];
__device__ float4 g_xr4[NBATCH*NPIX];
__device__ float4 g_ps4[NPTOT];
__device__ float  g_params[NBATCH*5*NPP];
__device__ float  g_smoothed[NBATCH*3*NPIX];
__device__ float  g_gb[NBATCH*NPIX];
__device__ float  g_yb[NBATCH*NPIX];
__device__ float  g_yi[NBATCH*NPIX];
__device__ float  g_stats[16];       // [6,7] yb sum/ss, [8,9] yi sum/ss
__device__ float2 g_cpart[NBATCH*3*16]; // per-block conv partial sums

// ---------------- helpers ----------------
__device__ __forceinline__ float wrap2pi(float v) {
    v = (v >= TWO_PI_F) ? v - TWO_PI_F : v;
    v = (v < 0.0f) ? v + TWO_PI_F : v;
    return v;
}
__device__ __forceinline__ float pow35(float u) {
    float u2 = u*u, u4 = u2*u2, u8 = u4*u4, u16 = u8*u8;
    return u16*u16*u2*u;
}
__device__ __forceinline__ float silu(float v) {
    return v / (1.0f + expf(-v));
}

// h = 0.5 + (1/pi) * atan(x), x pre-scaled by 1/eta (=100)
// sign folded into the odd polynomial; deg-9 minimax, err(h) ~ 3e-6
__device__ __forceinline__ float fast_hs(float x) {
    float inv;
    asm("rcp.approx.f32 %0, %1;" : "=f"(inv) : "f"(x));
    bool  big = fabsf(x) > 1.0f;
    float t = big ? inv : x;
    float s = t * t;
    float p =           0.0208351f;
    p = fmaf(p, s, -0.0851330f);
    p = fmaf(p, s,  0.1801410f);
    p = fmaf(p, s, -0.3302995f);
    p = fmaf(p, s,  0.9998660f);
    float r0 = t * p;
    float cs = copysignf(1.5707963267948966f, x);
    float r  = big ? (cs - r0) : r0;
    return fmaf(INV_PI_F, r, 0.5f);
}

// Candidate with sign- and 1/eta- folded line coefficients.
struct Cand {
    float A1x,A1y,A3x,A3y,A4x,A4y,A2x,A2y;
    float sg13, sg42, off13s, off42s;
    float x0, y0;
};

__device__ __forceinline__ Cand make_cand(const float cp[5]) {
    Cand K;
    K.x0 = cp[3]; K.y0 = cp[4];
    float m0 = wrap2pi(cp[0]), m1 = wrap2pi(cp[1]), m2 = wrap2pi(cp[2]);
    float lo = fminf(m0, m1), hi = fmaxf(m0, m1);
    float a1 = fminf(lo, m2);
    float a3 = fmaxf(hi, m2);
    float a2 = fmaxf(lo, fminf(hi, m2));
    // hm = mod2pi(0.5(a1-a3)) >= pi  <=>  a3 > a1  (range analysis)
    float a4 = 0.5f*(a1 + a3) + ((a3 > a1) ? PI_F : 0.0f);
    float d13 = a3 - a1;                       // in [0, 2pi)
    float m   = a2 - a4;                       // in (-2pi, 0]
    float d42 = (m < 0.0f) ? m + TWO_PI_F : m;
    K.sg13 = (d13 < PI_F) ? 1.0f : -1.0f;
    K.sg42 = (d42 < PI_F) ? 1.0f : -1.0f;
    K.off13s = 10.0f * pow35(d13 * INV_PI_F - 1.0f);  // 100*0.1*g
    K.off42s = 10.0f * pow35(d42 * INV_PI_F - 1.0f);
    float s1,c1,s2,c2,s3,c3,s4,c4;
    __sincosf(a1, &s1, &c1);
    __sincosf(a2, &s2, &c2);
    __sincosf(a3, &s3, &c3);
    __sincosf(a4, &s4, &c4);
    float f13 = 100.0f * K.sg13, f42 = 100.0f * K.sg42;
    K.A1x = -f13 * s1;  K.A1y =  f13 * c1;
    K.A3x =  f13 * s3;  K.A3y = -f13 * c3;
    K.A4x = -f42 * s4;  K.A4y =  f42 * c4;
    K.A2x =  f42 * s2;  K.A2y = -f42 * c2;
    return K;
}

__device__ __forceinline__ void dists_scaled(const Cand& K, float dx,
                                             float T1, float T3, float T4, float T2,
                                             float& d13s, float& d42s) {
    float l1 = fmaf(K.A1x, dx, T1);
    float l3 = fmaf(K.A3x, dx, T3);
    float l4 = fmaf(K.A4x, dx, T4);
    float l2 = fmaf(K.A2x, dx, T2);
    d13s = fmaf(K.sg13, fminf(l1, l3), K.off13s);
    d42s = fmaf(K.sg42, fminf(l4, l2), K.off42s);
}

__device__ __forceinline__ float cand_range(int ip, int q) {
    return (ip < 3) ? (float)q * (TWO_PI_F / 31.0f)
                    : (-3.0f + (float)q * 0.2f);
}

// ---------------- kernels ----------------
__global__ void k_conv(const float* __restrict__ x, const float* __restrict__ rw) {
    int gt = blockIdx.x * 256 + threadIdx.x;
    // fused zero of g_params (consumed later by k_step)
    for (int i = gt; i < NBATCH*5*NPP; i += NBATCH*3*16*256) g_params[i] = 0.0f;

    int bo = blockIdx.x >> 4;
    int chunk = blockIdx.x & 15;
    int b = bo / 3, o = bo % 3;
    int pix = chunk * 256 + threadIdx.x;
    const float* xp = x + (size_t)b * CINN * NPIX + pix;
    float acc = 0.0f;
    #pragma unroll
    for (int c = 0; c < CINN; c++)
        acc = fmaf(xp[c * NPIX], rw[o * CINN + c], acc);
    g_y[(b*3 + o) * NPIX + pix] = acc;

    __shared__ float s1[256], s2[256];
    s1[threadIdx.x] = acc; s2[threadIdx.x] = acc * acc;
    __syncthreads();
    for (int s = 128; s > 0; s >>= 1) {
        if (threadIdx.x < s) { s1[threadIdx.x] += s1[threadIdx.x+s]; s2[threadIdx.x] += s2[threadIdx.x+s]; }
        __syncthreads();
    }
    if (threadIdx.x == 0) g_cpart[blockIdx.x] = make_float2(s1[0], s2[0]);
}

__global__ void k_bnsilu(const float* __restrict__ gamma, const float* __restrict__ beta) {
    int t = blockIdx.x * 256 + threadIdx.x;
    int b = t >> 12, pix = t & (NPIX - 1);
    float v[3];
    #pragma unroll
    for (int c = 0; c < 3; c++) {
        float s = 0.0f, ss = 0.0f;
        #pragma unroll
        for (int b2 = 0; b2 < NBATCH; b2++)
            #pragma unroll
            for (int ch = 0; ch < 16; ch++) {
                float2 pv = g_cpart[(b2*3 + c) * 16 + ch];
                s += pv.x; ss += pv.y;
            }
        float m   = s  * (1.0f / NSTAT);
        float var = ss * (1.0f / NSTAT) - m * m;
        float y   = g_y[(b*3 + c) * NPIX + pix];
        float n   = gamma[c] * (y - m) * rsqrtf(var + 1e-5f) + beta[c];
        v[c] = silu(n);
    }
    g_xr4[t] = make_float4(v[0], v[1], v[2], 0.0f);
}

// per-patch channel sums + fused zeroing of fold buffers / stats
__global__ void k_psum() {
    int gt = blockIdx.x * 256 + threadIdx.x;
    int total = gridDim.x * 256;
    for (int i = gt; i < NBATCH*3*NPIX; i += total) g_smoothed[i] = 0.0f;
    for (int i = gt; i < NBATCH*NPIX;   i += total) g_gb[i]       = 0.0f;
    if (gt < 16) g_stats[gt] = 0.0f;

    int P  = gt >> 3, xr = gt & 7;
    float s0 = 0.0f, s1 = 0.0f, s2 = 0.0f;
    if (P < NPTOT) {
        int b = P / NPP, pp = P - b * NPP;
        int hp = pp / HPN, wp = pp - hp * HPN;
        const float4* row = g_xr4 + b * NPIX + (hp + xr) * WW + wp;
        #pragma unroll
        for (int yc = 0; yc < PSZ; yc++) {
            float4 v = __ldg(row + yc);
            s0 += v.x; s1 += v.y; s2 += v.z;
        }
    }
    #pragma unroll
    for (int off = 4; off > 0; off >>= 1) {
        s0 += __shfl_down_sync(0xffffffffu, s0, off, 8);
        s1 += __shfl_down_sync(0xffffffffu, s1, off, 8);
        s2 += __shfl_down_sync(0xffffffffu, s2, off, 8);
    }
    if (xr == 0 && P < NPTOT) g_ps4[P] = make_float4(s0, s1, s2, 0.0f);
}

// warp-per-patch: lane = candidate, shfl argmin, no smem/barriers
__global__ void __launch_bounds__(256, 4) k_step(int ip) {
    int wid  = threadIdx.x >> 5;
    int lane = threadIdx.x & 31;
    int P = blockIdx.x * 8 + wid;
    if (P >= NPTOT) return;                  // warp-uniform exit

    int b = P / NPP, pp = P - b * NPP;
    int hp = pp / HPN, wp = pp - hp * HPN;
    float p[5];
    #pragma unroll
    for (int j = 0; j < 5; j++) p[j] = g_params[(b*5 + j) * NPP + pp];
    float pbase = p[ip];

    int q = (lane < NV) ? lane : (NV - 1);   // lane 31 duplicates q=30
    float cp[5];
    #pragma unroll
    for (int j = 0; j < 5; j++) cp[j] = p[j];
    cp[ip] += cand_range(ip, q);

    Cand K = make_cand(cp);
    const float4* tile = g_xr4 + b * NPIX + hp * WW + wp;
    float4 S = __ldg(&g_ps4[P]);

    float dxv[PSZ];
    #pragma unroll
    for (int yc = 0; yc < PSZ; yc++)
        dxv[yc] = (-1.0f + (float)yc * (2.0f/7.0f)) - K.x0;

    float sw0=0.f, sw1=0.f;
    float cn00=0.f,cn01=0.f, cn10=0.f,cn11=0.f, cn20=0.f,cn21=0.f;
    float G00=0.f,G11=0.f,G01=0.f;

    #pragma unroll 1
    for (int xr = 0; xr < PSZ; xr++) {
        float dy = (-1.0f + (float)xr * (2.0f/7.0f)) - K.y0;
        float T1 = K.A1y*dy, T3 = K.A3y*dy, T4 = K.A4y*dy, T2 = K.A2y*dy;
        const float4* row = tile + xr * WW;
        #pragma unroll
        for (int yc = 0; yc < PSZ; yc++) {
            float d13s, d42s;
            dists_scaled(K, dxv[yc], T1, T3, T4, T2, d13s, d42s);
            float h0 = fast_hs(d13s);
            float h1 = fast_hs(d42s);
            float w0 = 1.0f - h0;
            float w1 = h0 * (1.0f - h1);
            float4 img = __ldg(row + yc);
            sw0 += w0; sw1 += w1;
            cn00 = fmaf(img.x, w0, cn00); cn01 = fmaf(img.x, w1, cn01);
            cn10 = fmaf(img.y, w0, cn10); cn11 = fmaf(img.y, w1, cn11);
            cn20 = fmaf(img.z, w0, cn20); cn21 = fmaf(img.z, w1, cn21);
            G00 = fmaf(w0, w0, G00); G11 = fmaf(w1, w1, G11); G01 = fmaf(w0, w1, G01);
        }
    }
    float sw2 = 64.0f - sw0 - sw1;
    float G02 = sw0 - G00 - G01;
    float G12 = sw1 - G01 - G11;
    float G22 = sw2 - G02 - G12;
    float i0 = 1.0f / (sw0 + 1e-10f);
    float i1 = 1.0f / (sw1 + 1e-10f);
    float i2 = 1.0f / (sw2 + 1e-10f);
    float Sc[3]  = {S.x, S.y, S.z};
    float n0a[3] = {cn00, cn10, cn20};
    float n1a[3] = {cn01, cn11, cn21};
    float score = 0.0f;
    #pragma unroll
    for (int c = 0; c < 3; c++) {
        float n0 = n0a[c], n1 = n1a[c];
        float n2 = Sc[c] - n0 - n1;
        float c0 = n0*i0, c1 = n1*i1, c2 = n2*i2;
        float quad = c0*c0*G00 + c1*c1*G11 + c2*c2*G22
                   + 2.0f*(c0*c1*G01 + c0*c2*G02 + c1*c2*G12);
        score += quad - 2.0f*(c0*n0 + c1*n1 + c2*n2);
    }

    // warp argmin (lowest q wins ties -> matches first-min semantics)
    float bl = score; int bq = q;
    #pragma unroll
    for (int off = 16; off > 0; off >>= 1) {
        float ol = __shfl_down_sync(0xffffffffu, bl, off);
        int   oq = __shfl_down_sync(0xffffffffu, bq, off);
        if (ol < bl || (ol == bl && oq < bq)) { bl = ol; bq = oq; }
    }
    if (lane == 0)
        g_params[(b*5 + ip) * NPP + pp] = pbase + cand_range(ip, bq);
}

__global__ void k_final() {
    int P = blockIdx.x * blockDim.x + threadIdx.x;
    if (P >= NPTOT) return;
    int b = P / NPP, pp = P - b * NPP;
    int hp = pp / HPN, wp = pp - hp * HPN;

    float cp[5];
    #pragma unroll
    for (int j = 0; j < 5; j++) cp[j] = g_params[(b*5 + j) * NPP + pp];
    Cand K = make_cand(cp);
    const float4* tile = g_xr4 + b * NPIX + hp * WW + wp;

    float dxv[PSZ];
    #pragma unroll
    for (int yc = 0; yc < PSZ; yc++)
        dxv[yc] = (-1.0f + (float)yc * (2.0f/7.0f)) - K.x0;

    float sw[3] = {0,0,0};
    float cn[3][3] = {{0,0,0},{0,0,0},{0,0,0}};
    #pragma unroll 1
    for (int xr = 0; xr < PSZ; xr++) {
        float dy = (-1.0f + (float)xr * (2.0f/7.0f)) - K.y0;
        float T1 = K.A1y*dy, T3 = K.A3y*dy, T4 = K.A4y*dy, T2 = K.A2y*dy;
        const float4* row = tile + xr * WW;
        #pragma unroll
        for (int yc = 0; yc < PSZ; yc++) {
            float d13s, d42s;
            dists_scaled(K, dxv[yc], T1, T3, T4, T2, d13s, d42s);
            float h0 = fast_hs(d13s);
            float h1 = fast_hs(d42s);
            float w0 = 1.0f - h0, w1 = h0 * (1.0f - h1), w2 = h0 * h1;
            float4 img = __ldg(row + yc);
            sw[0] += w0; sw[1] += w1; sw[2] += w2;
            cn[0][0] = fmaf(img.x,w0,cn[0][0]); cn[0][1] = fmaf(img.x,w1,cn[0][1]); cn[0][2] = fmaf(img.x,w2,cn[0][2]);
            cn[1][0] = fmaf(img.y,w0,cn[1][0]); cn[1][1] = fmaf(img.y,w1,cn[1][1]); cn[1][2] = fmaf(img.y,w2,cn[1][2]);
            cn[2][0] = fmaf(img.z,w0,cn[2][0]); cn[2][1] = fmaf(img.z,w1,cn[2][1]); cn[2][2] = fmaf(img.z,w2,cn[2][2]);
        }
    }
    float col[3][3];
    #pragma unroll
    for (int k = 0; k < 3; k++) {
        float inv = 1.0f / (sw[k] + 1e-10f);
        col[0][k] = cn[0][k] * inv;
        col[1][k] = cn[1][k] * inv;
        col[2][k] = cn[2][k] * inv;
    }

    #pragma unroll 1
    for (int xr = 0; xr < PSZ; xr++) {
        float dy = (-1.0f + (float)xr * (2.0f/7.0f)) - K.y0;
        float T1 = K.A1y*dy, T3 = K.A3y*dy, T4 = K.A4y*dy, T2 = K.A2y*dy;
        int hh = xr + hp;
        #pragma unroll
        for (int yc = 0; yc < PSZ; yc++) {
            float d13s, d42s;
            dists_scaled(K, dxv[yc], T1, T3, T4, T2, d13s, d42s);
            float h0 = fast_hs(d13s);
            float h1 = fast_hs(d42s);
            float w0 = 1.0f - h0, w1 = h0 * (1.0f - h1), w2 = h0 * h1;
            int opix = hh * WW + yc + wp;
            #pragma unroll
            for (int c = 0; c < 3; c++) {
                float pv = w0*col[c][0] + w1*col[c][1] + w2*col[c][2];
                atomicAdd(&g_smoothed[(b*3 + c) * NPIX + opix], pv);
            }
            // scaled dists: mad' = 100*mad; lb = 1/(1+(mad'*0.2)^2)
            float d1 = d13s, d2 = d42s;
            float mad = (d1 < 0.0f) ? -d1
                      : ((d2 < 0.0f) ? fminf(d1, -d2) : fminf(d1, d2));
            float r = mad * 0.2f;
            float lb = 1.0f / (1.0f + r * r);
            atomicAdd(&g_gb[b * NPIX + opix], lb);
        }
    }
}

__global__ void k_post1(const float* __restrict__ fbw, const float* __restrict__ fiw) {
    int t = blockIdx.x * 256 + threadIdx.x;
    int b = t >> 12, pix = t & (NPIX - 1);
    int h = pix >> 6, w = pix & 63;
    int ch = min(min(h + 1, HH - h), PSZ);
    int cw = min(min(w + 1, WW - w), PSZ);
    float inv = 1.0f / (float)(ch * cw);

    float sm0 = g_smoothed[(b*3 + 0) * NPIX + pix] * inv;
    float sm1 = g_smoothed[(b*3 + 1) * NPIX + pix] * inv;
    float sm2 = g_smoothed[(b*3 + 2) * NPIX + pix] * inv;
    float yi = sm0 * fiw[0] + sm1 * fiw[1] + sm2 * fiw[2];
    float gbv = g_gb[t] * inv;
    float yb = gbv * fbw[0] + gbv * fbw[1] + gbv * fbw[2];
    g_yi[t] = yi;
    g_yb[t] = yb;

    __shared__ float sA[256], sB[256];
    sA[threadIdx.x] = yb; sB[threadIdx.x] = yb * yb;
    __syncthreads();
    for (int s = 128; s > 0; s >>= 1) {
        if (threadIdx.x < s) { sA[threadIdx.x] += sA[threadIdx.x+s]; sB[threadIdx.x] += sB[threadIdx.x+s]; }
        __syncthreads();
    }
    if (threadIdx.x == 0) { atomicAdd(&g_stats[6], sA[0]); atomicAdd(&g_stats[7], sB[0]); }
    __syncthreads();
    sA[threadIdx.x] = yi; sB[threadIdx.x] = yi * yi;
    __syncthreads();
    for (int s = 128; s > 0; s >>= 1) {
        if (threadIdx.x < s) { sA[threadIdx.x] += sA[threadIdx.x+s]; sB[threadIdx.x] += sB[threadIdx.x+s]; }
        __syncthreads();
    }
    if (threadIdx.x == 0) { atomicAdd(&g_stats[8], sA[0]); atomicAdd(&g_stats[9], sB[0]); }
}

__global__ void k_out(float* __restrict__ out,
                      const float* __restrict__ fbg, const float* __restrict__ fbb,
                      const float* __restrict__ fig, const float* __restrict__ fib) {
    int t = blockIdx.x * 256 + threadIdx.x;
    float mb = g_stats[6] * (1.0f / NSTAT);
    float vb = g_stats[7] * (1.0f / NSTAT) - mb * mb;
    float nb = fbg[0] * (g_yb[t] - mb) * rsqrtf(vb + 1e-5f) + fbb[0];
    out[t] = silu(nb);

    float mi = g_stats[8] * (1.0f / NSTAT);
    float vi = g_stats[9] * (1.0f / NSTAT) - mi * mi;
    float ni = fig[0] * (g_yi[t] - mi) * rsqrtf(vi + 1e-5f) + fib[0];
    out[NBATCH * NPIX + t] = silu(ni);
}

// ---------------- launch ----------------
extern "C" void kernel_launch(void* const* d_in, const int* in_sizes, int n_in,
                              void* d_out, int out_size) {
    const float* x   = (const float*)d_in[0];
    const float* rw  = (const float*)d_in[1];
    const float* rg  = (const float*)d_in[2];
    const float* rb  = (const float*)d_in[3];
    const float* fbw = (const float*)d_in[4];
    const float* fbg = (const float*)d_in[5];
    const float* fbb = (const float*)d_in[6];
    const float* fiw = (const float*)d_in[7];
    const float* fig = (const float*)d_in[8];
    const float* fib = (const float*)d_in[9];
    float* out = (float*)d_out;

    k_conv<<<NBATCH * 3 * 16, 256>>>(x, rw);
    k_bnsilu<<<32, 256>>>(rg, rb);
    k_psum<<<(NPTOT * 8 + 255) / 256, 256>>>();
    for (int i = 0; i < 5; i++)
        k_step<<<(NPTOT + 7) / 8, 256>>>(i);
    k_final<<<(NPTOT + 255) / 256, 256>>>();
    k_post1<<<32, 256>>>(fbw, fiw);
    k_out<<<32, 256>>>(out, fbg, fbb, fig, fib);
}

// round 6
// speedup vs baseline: 1.2503x; 1.0704x over previous
#include <cuda_runtime.h>
#include <math.h>

#define TWO_PI_F 6.28318530717958647692f
#define PI_F     3.14159265358979323846f
#define INV_PI_F 0.31830988618367094f

#define PSZ   8
#define HH    64
#define WW    64
#define HPN   57
#define NPP   (HPN*HPN)        // 3249
#define NBATCH 2
#define NPTOT (NBATCH*NPP)     // 6498
#define NV    31
#define CINN  32
#define NPIX  (HH*WW)          // 4096
#define NSTAT 8192

// ---------------- device scratch ----------------
__device__ float  g_y[NBATCH*3*NPIX];
__device__ float4 g_xr4[NBATCH*NPIX];
__device__ float4 g_ps4[NPTOT];
__device__ float  g_params[NBATCH*5*NPP];
__device__ float  g_smoothed[NBATCH*3*NPIX];
__device__ float  g_gb[NBATCH*NPIX];
__device__ float  g_yb[NBATCH*NPIX];
__device__ float  g_yi[NBATCH*NPIX];
__device__ float  g_stats[16];
__device__ float2 g_cpart[NBATCH*3*16];

// ---------------- helpers ----------------
__device__ __forceinline__ float wrap2pi(float v) {
    v = (v >= TWO_PI_F) ? v - TWO_PI_F : v;
    v = (v < 0.0f) ? v + TWO_PI_F : v;
    return v;
}
__device__ __forceinline__ float pow35(float u) {
    float u2 = u*u, u4 = u2*u2, u8 = u4*u4, u16 = u8*u8;
    return u16*u16*u2*u;
}
__device__ __forceinline__ float silu(float v) {
    return v / (1.0f + expf(-v));
}

// h = 0.5 + (1/pi) * atan(x), x pre-scaled by 1/eta (=100)
__device__ __forceinline__ float fast_hs(float x) {
    float inv;
    asm("rcp.approx.f32 %0, %1;" : "=f"(inv) : "f"(x));
    bool  big = fabsf(x) > 1.0f;
    float t = big ? inv : x;
    float s = t * t;
    float p =           0.0208351f;
    p = fmaf(p, s, -0.0851330f);
    p = fmaf(p, s,  0.1801410f);
    p = fmaf(p, s, -0.3302995f);
    p = fmaf(p, s,  0.9998660f);
    float r0 = t * p;
    float cs = copysignf(1.5707963267948966f, x);
    float r  = big ? (cs - r0) : r0;
    return fmaf(INV_PI_F, r, 0.5f);
}

struct Cand {
    float A1x,A1y,A3x,A3y,A4x,A4y,A2x,A2y;
    float sg13, sg42, off13s, off42s;
    float x0, y0;
};

__device__ __forceinline__ Cand make_cand(const float cp[5]) {
    Cand K;
    K.x0 = cp[3]; K.y0 = cp[4];
    float m0 = wrap2pi(cp[0]), m1 = wrap2pi(cp[1]), m2 = wrap2pi(cp[2]);
    float lo = fminf(m0, m1), hi = fmaxf(m0, m1);
    float a1 = fminf(lo, m2);
    float a3 = fmaxf(hi, m2);
    float a2 = fmaxf(lo, fminf(hi, m2));
    float a4 = 0.5f*(a1 + a3) + ((a3 > a1) ? PI_F : 0.0f);
    float d13 = a3 - a1;
    float m   = a2 - a4;
    float d42 = (m < 0.0f) ? m + TWO_PI_F : m;
    K.sg13 = (d13 < PI_F) ? 1.0f : -1.0f;
    K.sg42 = (d42 < PI_F) ? 1.0f : -1.0f;
    K.off13s = 10.0f * pow35(d13 * INV_PI_F - 1.0f);
    K.off42s = 10.0f * pow35(d42 * INV_PI_F - 1.0f);
    float s1,c1,s2,c2,s3,c3,s4,c4;
    __sincosf(a1, &s1, &c1);
    __sincosf(a2, &s2, &c2);
    __sincosf(a3, &s3, &c3);
    __sincosf(a4, &s4, &c4);
    float f13 = 100.0f * K.sg13, f42 = 100.0f * K.sg42;
    K.A1x = -f13 * s1;  K.A1y =  f13 * c1;
    K.A3x =  f13 * s3;  K.A3y = -f13 * c3;
    K.A4x = -f42 * s4;  K.A4y =  f42 * c4;
    K.A2x =  f42 * s2;  K.A2y = -f42 * c2;
    return K;
}

__device__ __forceinline__ void dists_scaled(const Cand& K, float dx,
                                             float T1, float T3, float T4, float T2,
                                             float& d13s, float& d42s) {
    float l1 = fmaf(K.A1x, dx, T1);
    float l3 = fmaf(K.A3x, dx, T3);
    float l4 = fmaf(K.A4x, dx, T4);
    float l2 = fmaf(K.A2x, dx, T2);
    d13s = fmaf(K.sg13, fminf(l1, l3), K.off13s);
    d42s = fmaf(K.sg42, fminf(l4, l2), K.off42s);
}

__device__ __forceinline__ float cand_range(int ip, int q) {
    return (ip < 3) ? (float)q * (TWO_PI_F / 31.0f)
                    : (-3.0f + (float)q * 0.2f);
}

// ---------------- kernels ----------------
__global__ void k_conv(const float* __restrict__ x, const float* __restrict__ rw) {
    int gt = blockIdx.x * 256 + threadIdx.x;
    for (int i = gt; i < NBATCH*5*NPP; i += NBATCH*3*16*256) g_params[i] = 0.0f;

    int bo = blockIdx.x >> 4;
    int chunk = blockIdx.x & 15;
    int b = bo / 3, o = bo % 3;
    int pix = chunk * 256 + threadIdx.x;
    const float* xp = x + (size_t)b * CINN * NPIX + pix;
    float acc = 0.0f;
    #pragma unroll
    for (int c = 0; c < CINN; c++)
        acc = fmaf(xp[c * NPIX], rw[o * CINN + c], acc);
    g_y[(b*3 + o) * NPIX + pix] = acc;

    __shared__ float s1[256], s2[256];
    s1[threadIdx.x] = acc; s2[threadIdx.x] = acc * acc;
    __syncthreads();
    for (int s = 128; s > 0; s >>= 1) {
        if (threadIdx.x < s) { s1[threadIdx.x] += s1[threadIdx.x+s]; s2[threadIdx.x] += s2[threadIdx.x+s]; }
        __syncthreads();
    }
    if (threadIdx.x == 0) g_cpart[blockIdx.x] = make_float2(s1[0], s2[0]);
}

__global__ void k_bnsilu(const float* __restrict__ gamma, const float* __restrict__ beta) {
    int t = blockIdx.x * 256 + threadIdx.x;
    int b = t >> 12, pix = t & (NPIX - 1);
    float v[3];
    #pragma unroll
    for (int c = 0; c < 3; c++) {
        float s = 0.0f, ss = 0.0f;
        #pragma unroll
        for (int b2 = 0; b2 < NBATCH; b2++)
            #pragma unroll
            for (int ch = 0; ch < 16; ch++) {
                float2 pv = g_cpart[(b2*3 + c) * 16 + ch];
                s += pv.x; ss += pv.y;
            }
        float m   = s  * (1.0f / NSTAT);
        float var = ss * (1.0f / NSTAT) - m * m;
        float y   = g_y[(b*3 + c) * NPIX + pix];
        float n   = gamma[c] * (y - m) * rsqrtf(var + 1e-5f) + beta[c];
        v[c] = silu(n);
    }
    g_xr4[t] = make_float4(v[0], v[1], v[2], 0.0f);
}

__global__ void k_psum() {
    int gt = blockIdx.x * 256 + threadIdx.x;
    int total = gridDim.x * 256;
    for (int i = gt; i < NBATCH*3*NPIX; i += total) g_smoothed[i] = 0.0f;
    for (int i = gt; i < NBATCH*NPIX;   i += total) g_gb[i]       = 0.0f;
    if (gt < 16) g_stats[gt] = 0.0f;

    int P  = gt >> 3, xr = gt & 7;
    float s0 = 0.0f, s1 = 0.0f, s2 = 0.0f;
    if (P < NPTOT) {
        int b = P / NPP, pp = P - b * NPP;
        int hp = pp / HPN, wp = pp - hp * HPN;
        const float4* row = g_xr4 + b * NPIX + (hp + xr) * WW + wp;
        #pragma unroll
        for (int yc = 0; yc < PSZ; yc++) {
            float4 v = __ldg(row + yc);
            s0 += v.x; s1 += v.y; s2 += v.z;
        }
    }
    #pragma unroll
    for (int off = 4; off > 0; off >>= 1) {
        s0 += __shfl_down_sync(0xffffffffu, s0, off, 8);
        s1 += __shfl_down_sync(0xffffffffu, s1, off, 8);
        s2 += __shfl_down_sync(0xffffffffu, s2, off, 8);
    }
    if (xr == 0 && P < NPTOT) g_ps4[P] = make_float4(s0, s1, s2, 0.0f);
}

// half-patch per warp: warp w -> patch (blockIdx*4 + w/2), rows [4*(w&1), 4*(w&1)+4)
// lane = candidate; odd-half warp dumps 11 accumulators to smem, even-half combines+scores
__global__ void __launch_bounds__(256, 4) k_step(int ip) {
    int wid  = threadIdx.x >> 5;
    int lane = threadIdx.x & 31;
    int wp_i = wid >> 1;          // patch slot in block (0..3)
    int half = wid & 1;
    int P = blockIdx.x * 4 + wp_i;
    bool valid = (P < NPTOT);

    __shared__ float sAcc[4][11][32];

    int b = 0, pp = 0;
    float pbase = 0.0f;
    float acc[11];
    #pragma unroll
    for (int s = 0; s < 11; s++) acc[s] = 0.0f;
    float4 S = make_float4(0,0,0,0);
    int q = (lane < NV) ? lane : (NV - 1);

    if (valid) {
        b = P / NPP; pp = P - b * NPP;
        int hp = pp / HPN, wpx = pp - hp * HPN;
        float p[5];
        #pragma unroll
        for (int j = 0; j < 5; j++) p[j] = g_params[(b*5 + j) * NPP + pp];
        pbase = p[ip];

        float cp[5];
        #pragma unroll
        for (int j = 0; j < 5; j++) cp[j] = p[j];
        cp[ip] += cand_range(ip, q);

        Cand K = make_cand(cp);
        const float4* tile = g_xr4 + b * NPIX + hp * WW + wpx;
        if (half == 0) S = __ldg(&g_ps4[P]);

        float dxv[PSZ];
        #pragma unroll
        for (int yc = 0; yc < PSZ; yc++)
            dxv[yc] = (-1.0f + (float)yc * (2.0f/7.0f)) - K.x0;

        int rbase = half * 4;
        #pragma unroll 1
        for (int xr = 0; xr < 4; xr++) {
            int row_i = rbase + xr;
            float dy = (-1.0f + (float)row_i * (2.0f/7.0f)) - K.y0;
            float T1 = K.A1y*dy, T3 = K.A3y*dy, T4 = K.A4y*dy, T2 = K.A2y*dy;
            const float4* row = tile + row_i * WW;
            #pragma unroll
            for (int yc = 0; yc < PSZ; yc++) {
                float d13s, d42s;
                dists_scaled(K, dxv[yc], T1, T3, T4, T2, d13s, d42s);
                float h0 = fast_hs(d13s);
                float h1 = fast_hs(d42s);
                float w0 = 1.0f - h0;
                float w1 = h0 * (1.0f - h1);
                float4 img = __ldg(row + yc);
                acc[0] += w0; acc[1] += w1;
                acc[2] = fmaf(img.x, w0, acc[2]); acc[3] = fmaf(img.x, w1, acc[3]);
                acc[4] = fmaf(img.y, w0, acc[4]); acc[5] = fmaf(img.y, w1, acc[5]);
                acc[6] = fmaf(img.z, w0, acc[6]); acc[7] = fmaf(img.z, w1, acc[7]);
                acc[8] = fmaf(w0, w0, acc[8]); acc[9] = fmaf(w1, w1, acc[9]);
                acc[10] = fmaf(w0, w1, acc[10]);
            }
        }
    }

    if (valid && half == 1) {
        #pragma unroll
        for (int s = 0; s < 11; s++) sAcc[wp_i][s][lane] = acc[s];
    }
    __syncthreads();

    if (valid && half == 0) {
        #pragma unroll
        for (int s = 0; s < 11; s++) acc[s] += sAcc[wp_i][s][lane];

        float sw0 = acc[0], sw1 = acc[1];
        float sw2 = 64.0f - sw0 - sw1;
        float G00 = acc[8], G11 = acc[9], G01 = acc[10];
        float G02 = sw0 - G00 - G01;
        float G12 = sw1 - G01 - G11;
        float G22 = sw2 - G02 - G12;
        float i0 = 1.0f / (sw0 + 1e-10f);
        float i1 = 1.0f / (sw1 + 1e-10f);
        float i2 = 1.0f / (sw2 + 1e-10f);
        float Sc[3]  = {S.x, S.y, S.z};
        float n0a[3] = {acc[2], acc[4], acc[6]};
        float n1a[3] = {acc[3], acc[5], acc[7]};
        float score = 0.0f;
        #pragma unroll
        for (int c = 0; c < 3; c++) {
            float n0 = n0a[c], n1 = n1a[c];
            float n2 = Sc[c] - n0 - n1;
            float c0 = n0*i0, c1 = n1*i1, c2 = n2*i2;
            float quad = c0*c0*G00 + c1*c1*G11 + c2*c2*G22
                       + 2.0f*(c0*c1*G01 + c0*c2*G02 + c1*c2*G12);
            score += quad - 2.0f*(c0*n0 + c1*n1 + c2*n2);
        }

        float bl = score; int bq = q;
        #pragma unroll
        for (int off = 16; off > 0; off >>= 1) {
            float ol = __shfl_down_sync(0xffffffffu, bl, off);
            int   oq = __shfl_down_sync(0xffffffffu, bq, off);
            if (ol < bl || (ol == bl && oq < bq)) { bl = ol; bq = oq; }
        }
        if (lane == 0)
            g_params[(b*5 + ip) * NPP + pp] = pbase + cand_range(ip, bq);
    }
}

__global__ void k_final() {
    int P = blockIdx.x * blockDim.x + threadIdx.x;
    if (P >= NPTOT) return;
    int b = P / NPP, pp = P - b * NPP;
    int hp = pp / HPN, wp = pp - hp * HPN;

    float cp[5];
    #pragma unroll
    for (int j = 0; j < 5; j++) cp[j] = g_params[(b*5 + j) * NPP + pp];
    Cand K = make_cand(cp);
    const float4* tile = g_xr4 + b * NPIX + hp * WW + wp;

    float dxv[PSZ];
    #pragma unroll
    for (int yc = 0; yc < PSZ; yc++)
        dxv[yc] = (-1.0f + (float)yc * (2.0f/7.0f)) - K.x0;

    float sw[3] = {0,0,0};
    float cn[3][3] = {{0,0,0},{0,0,0},{0,0,0}};
    #pragma unroll 1
    for (int xr = 0; xr < PSZ; xr++) {
        float dy = (-1.0f + (float)xr * (2.0f/7.0f)) - K.y0;
        float T1 = K.A1y*dy, T3 = K.A3y*dy, T4 = K.A4y*dy, T2 = K.A2y*dy;
        const float4* row = tile + xr * WW;
        #pragma unroll
        for (int yc = 0; yc < PSZ; yc++) {
            float d13s, d42s;
            dists_scaled(K, dxv[yc], T1, T3, T4, T2, d13s, d42s);
            float h0 = fast_hs(d13s);
            float h1 = fast_hs(d42s);
            float w0 = 1.0f - h0, w1 = h0 * (1.0f - h1), w2 = h0 * h1;
            float4 img = __ldg(row + yc);
            sw[0] += w0; sw[1] += w1; sw[2] += w2;
            cn[0][0] = fmaf(img.x,w0,cn[0][0]); cn[0][1] = fmaf(img.x,w1,cn[0][1]); cn[0][2] = fmaf(img.x,w2,cn[0][2]);
            cn[1][0] = fmaf(img.y,w0,cn[1][0]); cn[1][1] = fmaf(img.y,w1,cn[1][1]); cn[1][2] = fmaf(img.y,w2,cn[1][2]);
            cn[2][0] = fmaf(img.z,w0,cn[2][0]); cn[2][1] = fmaf(img.z,w1,cn[2][1]); cn[2][2] = fmaf(img.z,w2,cn[2][2]);
        }
    }
    float col[3][3];
    #pragma unroll
    for (int k = 0; k < 3; k++) {
        float inv = 1.0f / (sw[k] + 1e-10f);
        col[0][k] = cn[0][k] * inv;
        col[1][k] = cn[1][k] * inv;
        col[2][k] = cn[2][k] * inv;
    }

    #pragma unroll 1
    for (int xr = 0; xr < PSZ; xr++) {
        float dy = (-1.0f + (float)xr * (2.0f/7.0f)) - K.y0;
        float T1 = K.A1y*dy, T3 = K.A3y*dy, T4 = K.A4y*dy, T2 = K.A2y*dy;
        int hh = xr + hp;
        #pragma unroll
        for (int yc = 0; yc < PSZ; yc++) {
            float d13s, d42s;
            dists_scaled(K, dxv[yc], T1, T3, T4, T2, d13s, d42s);
            float h0 = fast_hs(d13s);
            float h1 = fast_hs(d42s);
            float w0 = 1.0f - h0, w1 = h0 * (1.0f - h1), w2 = h0 * h1;
            int opix = hh * WW + yc + wp;
            #pragma unroll
            for (int c = 0; c < 3; c++) {
                float pv = w0*col[c][0] + w1*col[c][1] + w2*col[c][2];
                atomicAdd(&g_smoothed[(b*3 + c) * NPIX + opix], pv);
            }
            float d1 = d13s, d2 = d42s;
            float mad = (d1 < 0.0f) ? -d1
                      : ((d2 < 0.0f) ? fminf(d1, -d2) : fminf(d1, d2));
            float r = mad * 0.2f;
            float lb = 1.0f / (1.0f + r * r);
            atomicAdd(&g_gb[b * NPIX + opix], lb);
        }
    }
}

__global__ void k_post1(const float* __restrict__ fbw, const float* __restrict__ fiw) {
    int t = blockIdx.x * 256 + threadIdx.x;
    int b = t >> 12, pix = t & (NPIX - 1);
    int h = pix >> 6, w = pix & 63;
    int ch = min(min(h + 1, HH - h), PSZ);
    int cw = min(min(w + 1, WW - w), PSZ);
    float inv = 1.0f / (float)(ch * cw);

    float sm0 = g_smoothed[(b*3 + 0) * NPIX + pix] * inv;
    float sm1 = g_smoothed[(b*3 + 1) * NPIX + pix] * inv;
    float sm2 = g_smoothed[(b*3 + 2) * NPIX + pix] * inv;
    float yi = sm0 * fiw[0] + sm1 * fiw[1] + sm2 * fiw[2];
    float gbv = g_gb[t] * inv;
    float yb = gbv * fbw[0] + gbv * fbw[1] + gbv * fbw[2];
    g_yi[t] = yi;
    g_yb[t] = yb;

    __shared__ float sA[256], sB[256];
    sA[threadIdx.x] = yb; sB[threadIdx.x] = yb * yb;
    __syncthreads();
    for (int s = 128; s > 0; s >>= 1) {
        if (threadIdx.x < s) { sA[threadIdx.x] += sA[threadIdx.x+s]; sB[threadIdx.x] += sB[threadIdx.x+s]; }
        __syncthreads();
    }
    if (threadIdx.x == 0) { atomicAdd(&g_stats[6], sA[0]); atomicAdd(&g_stats[7], sB[0]); }
    __syncthreads();
    sA[threadIdx.x] = yi; sB[threadIdx.x] = yi * yi;
    __syncthreads();
    for (int s = 128; s > 0; s >>= 1) {
        if (threadIdx.x < s) { sA[threadIdx.x] += sA[threadIdx.x+s]; sB[threadIdx.x] += sB[threadIdx.x+s]; }
        __syncthreads();
    }
    if (threadIdx.x == 0) { atomicAdd(&g_stats[8], sA[0]); atomicAdd(&g_stats[9], sB[0]); }
}

__global__ void k_out(float* __restrict__ out,
                      const float* __restrict__ fbg, const float* __restrict__ fbb,
                      const float* __restrict__ fig, const float* __restrict__ fib) {
    int t = blockIdx.x * 256 + threadIdx.x;
    float mb = g_stats[6] * (1.0f / NSTAT);
    float vb = g_stats[7] * (1.0f / NSTAT) - mb * mb;
    float nb = fbg[0] * (g_yb[t] - mb) * rsqrtf(vb + 1e-5f) + fbb[0];
    out[t] = silu(nb);

    float mi = g_stats[8] * (1.0f / NSTAT);
    float vi = g_stats[9] * (1.0f / NSTAT) - mi * mi;
    float ni = fig[0] * (g_yi[t] - mi) * rsqrtf(vi + 1e-5f) + fib[0];
    out[NBATCH * NPIX + t] = silu(ni);
}

// ---------------- launch ----------------
extern "C" void kernel_launch(void* const* d_in, const int* in_sizes, int n_in,
                              void* d_out, int out_size) {
    const float* x   = (const float*)d_in[0];
    const float* rw  = (const float*)d_in[1];
    const float* rg  = (const float*)d_in[2];
    const float* rb  = (const float*)d_in[3];
    const float* fbw = (const float*)d_in[4];
    const float* fbg = (const float*)d_in[5];
    const float* fbb = (const float*)d_in[6];
    const float* fiw = (const float*)d_in[7];
    const float* fig = (const float*)d_in[8];
    const float* fib = (const float*)d_in[9];
    float* out = (float*)d_out;

    k_conv<<<NBATCH * 3 * 16, 256>>>(x, rw);
    k_bnsilu<<<32, 256>>>(rg, rb);
    k_psum<<<(NPTOT * 8 + 255) / 256, 256>>>();
    for (int i = 0; i < 5; i++)
        k_step<<<(NPTOT + 3) / 4, 256>>>(i);
    k_final<<<(NPTOT + 255) / 256, 256>>>();
    k_post1<<<32, 256>>>(fbw, fiw);
    k_out<<<32, 256>>>(out, fbg, fbb, fig, fib);
}

// round 7
// speedup vs baseline: 1.5085x; 1.2065x over previous
#include <cuda_runtime.h>
#include <math.h>

#define TWO_PI_F 6.28318530717958647692f
#define PI_F     3.14159265358979323846f
#define INV_PI_F 0.31830988618367094f

#define PSZ   8
#define HH    64
#define WW    64
#define HPN   57
#define NPP   (HPN*HPN)        // 3249
#define NBATCH 2
#define NPTOT (NBATCH*NPP)     // 6498
#define NV    31
#define CINN  32
#define NPIX  (HH*WW)          // 4096
#define NSTAT 8192

// ---------------- device scratch ----------------
__device__ float  g_y[NBATCH*3*NPIX];
__device__ float4 g_xr4[NBATCH*NPIX];
__device__ float4 g_ps4[NPTOT];
__device__ float  g_smoothed[NBATCH*3*NPIX];
__device__ float  g_gb[NBATCH*NPIX];
__device__ float  g_yb[NBATCH*NPIX];
__device__ float  g_yi[NBATCH*NPIX];
__device__ float  g_stats[16];
__device__ float2 g_cpart[NBATCH*3*16];

// ---------------- helpers ----------------
__device__ __forceinline__ float wrap2pi(float v) {
    v = (v >= TWO_PI_F) ? v - TWO_PI_F : v;
    v = (v < 0.0f) ? v + TWO_PI_F : v;
    return v;
}
__device__ __forceinline__ float pow35(float u) {
    float u2 = u*u, u4 = u2*u2, u8 = u4*u4, u16 = u8*u8;
    return u16*u16*u2*u;
}
__device__ __forceinline__ float silu(float v) {
    return v / (1.0f + expf(-v));
}

// h = 0.5 + (1/pi) * atan(x), x pre-scaled by 1/eta (=100)
__device__ __forceinline__ float fast_hs(float x) {
    float inv;
    asm("rcp.approx.f32 %0, %1;" : "=f"(inv) : "f"(x));
    bool  big = fabsf(x) > 1.0f;
    float t = big ? inv : x;
    float s = t * t;
    float p =           0.0208351f;
    p = fmaf(p, s, -0.0851330f);
    p = fmaf(p, s,  0.1801410f);
    p = fmaf(p, s, -0.3302995f);
    p = fmaf(p, s,  0.9998660f);
    float r0 = t * p;
    float cs = copysignf(1.5707963267948966f, x);
    float r  = big ? (cs - r0) : r0;
    return fmaf(INV_PI_F, r, 0.5f);
}

struct Cand {
    float A1x,A1y,A3x,A3y,A4x,A4y,A2x,A2y;
    float sg13, sg42, off13s, off42s;
    float x0, y0;
};

__device__ __forceinline__ Cand make_cand(const float cp[5]) {
    Cand K;
    K.x0 = cp[3]; K.y0 = cp[4];
    float m0 = wrap2pi(cp[0]), m1 = wrap2pi(cp[1]), m2 = wrap2pi(cp[2]);
    float lo = fminf(m0, m1), hi = fmaxf(m0, m1);
    float a1 = fminf(lo, m2);
    float a3 = fmaxf(hi, m2);
    float a2 = fmaxf(lo, fminf(hi, m2));
    float a4 = 0.5f*(a1 + a3) + ((a3 > a1) ? PI_F : 0.0f);
    float d13 = a3 - a1;
    float m   = a2 - a4;
    float d42 = (m < 0.0f) ? m + TWO_PI_F : m;
    K.sg13 = (d13 < PI_F) ? 1.0f : -1.0f;
    K.sg42 = (d42 < PI_F) ? 1.0f : -1.0f;
    K.off13s = 10.0f * pow35(d13 * INV_PI_F - 1.0f);
    K.off42s = 10.0f * pow35(d42 * INV_PI_F - 1.0f);
    float s1,c1,s2,c2,s3,c3,s4,c4;
    __sincosf(a1, &s1, &c1);
    __sincosf(a2, &s2, &c2);
    __sincosf(a3, &s3, &c3);
    __sincosf(a4, &s4, &c4);
    float f13 = 100.0f * K.sg13, f42 = 100.0f * K.sg42;
    K.A1x = -f13 * s1;  K.A1y =  f13 * c1;
    K.A3x =  f13 * s3;  K.A3y = -f13 * c3;
    K.A4x = -f42 * s4;  K.A4y =  f42 * c4;
    K.A2x =  f42 * s2;  K.A2y = -f42 * c2;
    return K;
}

__device__ __forceinline__ void dists_scaled(const Cand& K, float dx,
                                             float T1, float T3, float T4, float T2,
                                             float& d13s, float& d42s) {
    float l1 = fmaf(K.A1x, dx, T1);
    float l3 = fmaf(K.A3x, dx, T3);
    float l4 = fmaf(K.A4x, dx, T4);
    float l2 = fmaf(K.A2x, dx, T2);
    d13s = fmaf(K.sg13, fminf(l1, l3), K.off13s);
    d42s = fmaf(K.sg42, fminf(l4, l2), K.off42s);
}

__device__ __forceinline__ float cand_range(int ip, int q) {
    return (ip < 3) ? (float)q * (TWO_PI_F / 31.0f)
                    : (-3.0f + (float)q * 0.2f);
}

// ---------------- kernels ----------------
__global__ void k_conv(const float* __restrict__ x, const float* __restrict__ rw) {
    int bo = blockIdx.x >> 4;
    int chunk = blockIdx.x & 15;
    int b = bo / 3, o = bo % 3;
    int pix = chunk * 256 + threadIdx.x;
    const float* xp = x + (size_t)b * CINN * NPIX + pix;
    float acc = 0.0f;
    #pragma unroll
    for (int c = 0; c < CINN; c++)
        acc = fmaf(xp[c * NPIX], rw[o * CINN + c], acc);
    g_y[(b*3 + o) * NPIX + pix] = acc;

    __shared__ float s1[256], s2[256];
    s1[threadIdx.x] = acc; s2[threadIdx.x] = acc * acc;
    __syncthreads();
    for (int s = 128; s > 0; s >>= 1) {
        if (threadIdx.x < s) { s1[threadIdx.x] += s1[threadIdx.x+s]; s2[threadIdx.x] += s2[threadIdx.x+s]; }
        __syncthreads();
    }
    if (threadIdx.x == 0) g_cpart[blockIdx.x] = make_float2(s1[0], s2[0]);
}

__global__ void k_bnsilu(const float* __restrict__ gamma, const float* __restrict__ beta) {
    int t = blockIdx.x * 256 + threadIdx.x;
    int b = t >> 12, pix = t & (NPIX - 1);
    float v[3];
    #pragma unroll
    for (int c = 0; c < 3; c++) {
        float s = 0.0f, ss = 0.0f;
        #pragma unroll
        for (int b2 = 0; b2 < NBATCH; b2++)
            #pragma unroll
            for (int ch = 0; ch < 16; ch++) {
                float2 pv = g_cpart[(b2*3 + c) * 16 + ch];
                s += pv.x; ss += pv.y;
            }
        float m   = s  * (1.0f / NSTAT);
        float var = ss * (1.0f / NSTAT) - m * m;
        float y   = g_y[(b*3 + c) * NPIX + pix];
        float n   = gamma[c] * (y - m) * rsqrtf(var + 1e-5f) + beta[c];
        v[c] = silu(n);
    }
    g_xr4[t] = make_float4(v[0], v[1], v[2], 0.0f);
}

__global__ void k_psum() {
    int gt = blockIdx.x * 256 + threadIdx.x;
    int total = gridDim.x * 256;
    for (int i = gt; i < NBATCH*3*NPIX; i += total) g_smoothed[i] = 0.0f;
    for (int i = gt; i < NBATCH*NPIX;   i += total) g_gb[i]       = 0.0f;
    if (gt < 16) g_stats[gt] = 0.0f;

    int P  = gt >> 3, xr = gt & 7;
    float s0 = 0.0f, s1 = 0.0f, s2 = 0.0f;
    if (P < NPTOT) {
        int b = P / NPP, pp = P - b * NPP;
        int hp = pp / HPN, wp = pp - hp * HPN;
        const float4* row = g_xr4 + b * NPIX + (hp + xr) * WW + wp;
        #pragma unroll
        for (int yc = 0; yc < PSZ; yc++) {
            float4 v = __ldg(row + yc);
            s0 += v.x; s1 += v.y; s2 += v.z;
        }
    }
    #pragma unroll
    for (int off = 4; off > 0; off >>= 1) {
        s0 += __shfl_down_sync(0xffffffffu, s0, off, 8);
        s1 += __shfl_down_sync(0xffffffffu, s1, off, 8);
        s2 += __shfl_down_sync(0xffffffffu, s2, off, 8);
    }
    if (xr == 0 && P < NPTOT) g_ps4[P] = make_float4(s0, s1, s2, 0.0f);
}

// Fused 5-step coordinate descent + finalize, one 64-thread block per patch.
// Steps: 2 warps x half-patch, lane = candidate, params in registers.
// Finalize: thread = pixel.
__global__ void __launch_bounds__(64, 16) k_opt() {
    int tid  = threadIdx.x;
    int wid  = tid >> 5;
    int lane = tid & 31;
    int P = blockIdx.x;
    int b = P / NPP, pp = P - b * NPP;
    int hp = pp / HPN, wpx = pp - hp * HPN;
    const float4* tile = g_xr4 + b * NPIX + hp * WW + wpx;
    float4 S = __ldg(&g_ps4[P]);

    __shared__ float sAcc[2][11][32];
    __shared__ float sRed[2][8];

    float p[5] = {0.f, 0.f, 0.f, 0.f, 0.f};
    int q = (lane < NV) ? lane : (NV - 1);

    #pragma unroll 1
    for (int ip = 0; ip < 5; ip++) {
        float cp[5];
        #pragma unroll
        for (int j = 0; j < 5; j++) cp[j] = p[j];
        cp[ip] += cand_range(ip, q);

        Cand K = make_cand(cp);

        float dxv[PSZ];
        #pragma unroll
        for (int yc = 0; yc < PSZ; yc++)
            dxv[yc] = (-1.0f + (float)yc * (2.0f/7.0f)) - K.x0;

        float acc[11];
        #pragma unroll
        for (int s = 0; s < 11; s++) acc[s] = 0.0f;

        int rbase = wid * 4;
        #pragma unroll 1
        for (int xr = 0; xr < 4; xr++) {
            int row_i = rbase + xr;
            float dy = (-1.0f + (float)row_i * (2.0f/7.0f)) - K.y0;
            float T1 = K.A1y*dy, T3 = K.A3y*dy, T4 = K.A4y*dy, T2 = K.A2y*dy;
            const float4* row = tile + row_i * WW;
            #pragma unroll
            for (int yc = 0; yc < PSZ; yc++) {
                float d13s, d42s;
                dists_scaled(K, dxv[yc], T1, T3, T4, T2, d13s, d42s);
                float h0 = fast_hs(d13s);
                float h1 = fast_hs(d42s);
                float w0 = 1.0f - h0;
                float w1 = h0 * (1.0f - h1);
                float4 img = __ldg(row + yc);
                acc[0] += w0; acc[1] += w1;
                acc[2] = fmaf(img.x, w0, acc[2]); acc[3] = fmaf(img.x, w1, acc[3]);
                acc[4] = fmaf(img.y, w0, acc[4]); acc[5] = fmaf(img.y, w1, acc[5]);
                acc[6] = fmaf(img.z, w0, acc[6]); acc[7] = fmaf(img.z, w1, acc[7]);
                acc[8] = fmaf(w0, w0, acc[8]); acc[9] = fmaf(w1, w1, acc[9]);
                acc[10] = fmaf(w0, w1, acc[10]);
            }
        }

        // exchange halves (both directions)
        #pragma unroll
        for (int s = 0; s < 11; s++) sAcc[wid][s][lane] = acc[s];
        __syncthreads();
        #pragma unroll
        for (int s = 0; s < 11; s++) acc[s] += sAcc[wid ^ 1][s][lane];

        // score (both warps, identical results)
        float sw0 = acc[0], sw1 = acc[1];
        float sw2 = 64.0f - sw0 - sw1;
        float G00 = acc[8], G11 = acc[9], G01 = acc[10];
        float G02 = sw0 - G00 - G01;
        float G12 = sw1 - G01 - G11;
        float G22 = sw2 - G02 - G12;
        float i0 = 1.0f / (sw0 + 1e-10f);
        float i1 = 1.0f / (sw1 + 1e-10f);
        float i2 = 1.0f / (sw2 + 1e-10f);
        float Sc[3]  = {S.x, S.y, S.z};
        float n0a[3] = {acc[2], acc[4], acc[6]};
        float n1a[3] = {acc[3], acc[5], acc[7]};
        float score = 0.0f;
        #pragma unroll
        for (int c = 0; c < 3; c++) {
            float n0 = n0a[c], n1 = n1a[c];
            float n2 = Sc[c] - n0 - n1;
            float c0 = n0*i0, c1 = n1*i1, c2 = n2*i2;
            float quad = c0*c0*G00 + c1*c1*G11 + c2*c2*G22
                       + 2.0f*(c0*c1*G01 + c0*c2*G02 + c1*c2*G12);
            score += quad - 2.0f*(c0*n0 + c1*n1 + c2*n2);
        }

        // butterfly argmin: every lane ends with the global best (lowest q on ties)
        float bl = score; int bq = q;
        #pragma unroll
        for (int off = 16; off > 0; off >>= 1) {
            float ol = __shfl_xor_sync(0xffffffffu, bl, off);
            int   oq = __shfl_xor_sync(0xffffffffu, bq, off);
            if (ol < bl || (ol == bl && oq < bq)) { bl = ol; bq = oq; }
        }
        p[ip] += cand_range(ip, bq);
        __syncthreads();   // protect sAcc reuse next step
    }

    // ---------- finalize: thread = pixel ----------
    Cand K = make_cand(p);
    int xr = tid >> 3, yc = tid & 7;
    float dy = (-1.0f + (float)xr * (2.0f/7.0f)) - K.y0;
    float dx = (-1.0f + (float)yc * (2.0f/7.0f)) - K.x0;
    float T1 = K.A1y*dy, T3 = K.A3y*dy, T4 = K.A4y*dy, T2 = K.A2y*dy;
    float d13s, d42s;
    dists_scaled(K, dx, T1, T3, T4, T2, d13s, d42s);
    float h0 = fast_hs(d13s);
    float h1 = fast_hs(d42s);
    float w0 = 1.0f - h0, w1 = h0 * (1.0f - h1), w2 = h0 * h1;
    float4 img = __ldg(tile + xr * WW + yc);

    float red[8] = {w0, w1, img.x*w0, img.x*w1, img.y*w0, img.y*w1, img.z*w0, img.z*w1};
    #pragma unroll
    for (int s = 0; s < 8; s++) {
        #pragma unroll
        for (int off = 16; off > 0; off >>= 1)
            red[s] += __shfl_down_sync(0xffffffffu, red[s], off);
    }
    if (lane == 0) {
        #pragma unroll
        for (int s = 0; s < 8; s++) sRed[wid][s] = red[s];
    }
    __syncthreads();
    float tot[8];
    #pragma unroll
    for (int s = 0; s < 8; s++) tot[s] = sRed[0][s] + sRed[1][s];

    float sw0 = tot[0], sw1 = tot[1];
    float sw2 = 64.0f - sw0 - sw1;
    float i0 = 1.0f / (sw0 + 1e-10f);
    float i1 = 1.0f / (sw1 + 1e-10f);
    float i2 = 1.0f / (sw2 + 1e-10f);
    float Sc[3] = {S.x, S.y, S.z};

    int opix = (xr + hp) * WW + (yc + wpx);
    #pragma unroll
    for (int c = 0; c < 3; c++) {
        float n0 = tot[2 + 2*c], n1 = tot[3 + 2*c];
        float n2 = Sc[c] - n0 - n1;
        float c0 = n0 * i0, c1 = n1 * i1, c2 = n2 * i2;
        float pv = w0*c0 + w1*c1 + w2*c2;
        atomicAdd(&g_smoothed[(b*3 + c) * NPIX + opix], pv);
    }
    float d1 = d13s, d2 = d42s;
    float mad = (d1 < 0.0f) ? -d1
              : ((d2 < 0.0f) ? fminf(d1, -d2) : fminf(d1, d2));
    float r = mad * 0.2f;   // scaled dists: mad' = 100*mad
    float lb = 1.0f / (1.0f + r * r);
    atomicAdd(&g_gb[b * NPIX + opix], lb);
}

__global__ void k_post1(const float* __restrict__ fbw, const float* __restrict__ fiw) {
    int t = blockIdx.x * 256 + threadIdx.x;
    int b = t >> 12, pix = t & (NPIX - 1);
    int h = pix >> 6, w = pix & 63;
    int ch = min(min(h + 1, HH - h), PSZ);
    int cw = min(min(w + 1, WW - w), PSZ);
    float inv = 1.0f / (float)(ch * cw);

    float sm0 = g_smoothed[(b*3 + 0) * NPIX + pix] * inv;
    float sm1 = g_smoothed[(b*3 + 1) * NPIX + pix] * inv;
    float sm2 = g_smoothed[(b*3 + 2) * NPIX + pix] * inv;
    float yi = sm0 * fiw[0] + sm1 * fiw[1] + sm2 * fiw[2];
    float gbv = g_gb[t] * inv;
    float yb = gbv * fbw[0] + gbv * fbw[1] + gbv * fbw[2];
    g_yi[t] = yi;
    g_yb[t] = yb;

    __shared__ float sA[256], sB[256];
    sA[threadIdx.x] = yb; sB[threadIdx.x] = yb * yb;
    __syncthreads();
    for (int s = 128; s > 0; s >>= 1) {
        if (threadIdx.x < s) { sA[threadIdx.x] += sA[threadIdx.x+s]; sB[threadIdx.x] += sB[threadIdx.x+s]; }
        __syncthreads();
    }
    if (threadIdx.x == 0) { atomicAdd(&g_stats[6], sA[0]); atomicAdd(&g_stats[7], sB[0]); }
    __syncthreads();
    sA[threadIdx.x] = yi; sB[threadIdx.x] = yi * yi;
    __syncthreads();
    for (int s = 128; s > 0; s >>= 1) {
        if (threadIdx.x < s) { sA[threadIdx.x] += sA[threadIdx.x+s]; sB[threadIdx.x] += sB[threadIdx.x+s]; }
        __syncthreads();
    }
    if (threadIdx.x == 0) { atomicAdd(&g_stats[8], sA[0]); atomicAdd(&g_stats[9], sB[0]); }
}

__global__ void k_out(float* __restrict__ out,
                      const float* __restrict__ fbg, const float* __restrict__ fbb,
                      const float* __restrict__ fig, const float* __restrict__ fib) {
    int t = blockIdx.x * 256 + threadIdx.x;
    float mb = g_stats[6] * (1.0f / NSTAT);
    float vb = g_stats[7] * (1.0f / NSTAT) - mb * mb;
    float nb = fbg[0] * (g_yb[t] - mb) * rsqrtf(vb + 1e-5f) + fbb[0];
    out[t] = silu(nb);

    float mi = g_stats[8] * (1.0f / NSTAT);
    float vi = g_stats[9] * (1.0f / NSTAT) - mi * mi;
    float ni = fig[0] * (g_yi[t] - mi) * rsqrtf(vi + 1e-5f) + fib[0];
    out[NBATCH * NPIX + t] = silu(ni);
}

// ---------------- launch ----------------
extern "C" void kernel_launch(void* const* d_in, const int* in_sizes, int n_in,
                              void* d_out, int out_size) {
    const float* x   = (const float*)d_in[0];
    const float* rw  = (const float*)d_in[1];
    const float* rg  = (const float*)d_in[2];
    const float* rb  = (const float*)d_in[3];
    const float* fbw = (const float*)d_in[4];
    const float* fbg = (const float*)d_in[5];
    const float* fbb = (const float*)d_in[6];
    const float* fiw = (const float*)d_in[7];
    const float* fig = (const float*)d_in[8];
    const float* fib = (const float*)d_in[9];
    float* out = (float*)d_out;

    k_conv<<<NBATCH * 3 * 16, 256>>>(x, rw);
    k_bnsilu<<<32, 256>>>(rg, rb);
    k_psum<<<(NPTOT * 8 + 255) / 256, 256>>>();
    k_opt<<<NPTOT, 64>>>();
    k_post1<<<32, 256>>>(fbw, fiw);
    k_out<<<32, 256>>>(out, fbg, fbb, fig, fib);
}

// round 8
// speedup vs baseline: 1.5433x; 1.0231x over previous
#include <cuda_runtime.h>
#include <math.h>

#define TWO_PI_F 6.28318530717958647692f
#define PI_F     3.14159265358979323846f
#define INV_PI_F 0.31830988618367094f

#define PSZ   8
#define HH    64
#define WW    64
#define HPN   57
#define NPP   (HPN*HPN)        // 3249
#define NBATCH 2
#define NPTOT (NBATCH*NPP)     // 6498
#define NV    31
#define CINN  32
#define NPIX  (HH*WW)          // 4096
#define NSTAT 8192

// ---------------- device scratch ----------------
__device__ float  g_y[NBATCH*3*NPIX];
__device__ float4 g_xr4[NBATCH*NPIX];
__device__ float4 g_ps4[NPTOT];
__device__ float  g_smoothed[NBATCH*3*NPIX];
__device__ float  g_gb[NBATCH*NPIX];
__device__ float  g_yb[NBATCH*NPIX];
__device__ float  g_yi[NBATCH*NPIX];
__device__ float  g_stats[16];
__device__ float2 g_cpart[NBATCH*3*16];

// ---------------- helpers ----------------
__device__ __forceinline__ float wrap2pi(float v) {
    v = (v >= TWO_PI_F) ? v - TWO_PI_F : v;
    v = (v < 0.0f) ? v + TWO_PI_F : v;
    return v;
}
__device__ __forceinline__ float pow35(float u) {
    float u2 = u*u, u4 = u2*u2, u8 = u4*u4, u16 = u8*u8;
    return u16*u16*u2*u;
}
__device__ __forceinline__ float silu(float v) {
    return v / (1.0f + expf(-v));
}

// h = 0.5 + (1/pi) * atan(x), x pre-scaled by 1/eta (=100)
__device__ __forceinline__ float fast_hs(float x) {
    float inv;
    asm("rcp.approx.f32 %0, %1;" : "=f"(inv) : "f"(x));
    bool  big = fabsf(x) > 1.0f;
    float t = big ? inv : x;
    float s = t * t;
    float p =           0.0208351f;
    p = fmaf(p, s, -0.0851330f);
    p = fmaf(p, s,  0.1801410f);
    p = fmaf(p, s, -0.3302995f);
    p = fmaf(p, s,  0.9998660f);
    float r0 = t * p;
    float cs = copysignf(1.5707963267948966f, x);
    float r  = big ? (cs - r0) : r0;
    return fmaf(INV_PI_F, r, 0.5f);
}

// Candidate: sign+1/eta folded line coefficients, x0 folded into row constants.
// l_k(px) = Akx * cc + (Aky * dy + Ck), cc = column coord (compile-time const)
struct Cand {
    float A1x,A1y,A3x,A3y,A4x,A4y,A2x,A2y;
    float C1,C3,C4,C2;
    float sg13, sg42, off13s, off42s;
    float y0;
};

__device__ __forceinline__ Cand make_cand(const float cp[5]) {
    Cand K;
    float x0 = cp[3]; K.y0 = cp[4];
    float m0 = wrap2pi(cp[0]), m1 = wrap2pi(cp[1]), m2 = wrap2pi(cp[2]);
    float lo = fminf(m0, m1), hi = fmaxf(m0, m1);
    float a1 = fminf(lo, m2);
    float a3 = fmaxf(hi, m2);
    float a2 = fmaxf(lo, fminf(hi, m2));
    float a4 = 0.5f*(a1 + a3) + ((a3 > a1) ? PI_F : 0.0f);
    float d13 = a3 - a1;
    float m   = a2 - a4;
    float d42 = (m < 0.0f) ? m + TWO_PI_F : m;
    K.sg13 = (d13 < PI_F) ? 1.0f : -1.0f;
    K.sg42 = (d42 < PI_F) ? 1.0f : -1.0f;
    K.off13s = 10.0f * pow35(d13 * INV_PI_F - 1.0f);
    K.off42s = 10.0f * pow35(d42 * INV_PI_F - 1.0f);
    float s1,c1,s2,c2,s3,c3,s4,c4;
    __sincosf(a1, &s1, &c1);
    __sincosf(a2, &s2, &c2);
    __sincosf(a3, &s3, &c3);
    __sincosf(a4, &s4, &c4);
    float f13 = 100.0f * K.sg13, f42 = 100.0f * K.sg42;
    K.A1x = -f13 * s1;  K.A1y =  f13 * c1;
    K.A3x =  f13 * s3;  K.A3y = -f13 * c3;
    K.A4x = -f42 * s4;  K.A4y =  f42 * c4;
    K.A2x =  f42 * s2;  K.A2y = -f42 * c2;
    K.C1 = -K.A1x * x0; K.C3 = -K.A3x * x0;
    K.C4 = -K.A4x * x0; K.C2 = -K.A2x * x0;
    return K;
}

__device__ __forceinline__ float cand_range(int ip, int q) {
    return (ip < 3) ? (float)q * (TWO_PI_F / 31.0f)
                    : (-3.0f + (float)q * 0.2f);
}

// ---------------- kernels ----------------
__global__ void k_conv(const float* __restrict__ x, const float* __restrict__ rw) {
    int bo = blockIdx.x >> 4;
    int chunk = blockIdx.x & 15;
    int b = bo / 3, o = bo % 3;
    int pix = chunk * 256 + threadIdx.x;
    const float* xp = x + (size_t)b * CINN * NPIX + pix;
    float acc = 0.0f;
    #pragma unroll
    for (int c = 0; c < CINN; c++)
        acc = fmaf(xp[c * NPIX], rw[o * CINN + c], acc);
    g_y[(b*3 + o) * NPIX + pix] = acc;

    __shared__ float s1[256], s2[256];
    s1[threadIdx.x] = acc; s2[threadIdx.x] = acc * acc;
    __syncthreads();
    for (int s = 128; s > 0; s >>= 1) {
        if (threadIdx.x < s) { s1[threadIdx.x] += s1[threadIdx.x+s]; s2[threadIdx.x] += s2[threadIdx.x+s]; }
        __syncthreads();
    }
    if (threadIdx.x == 0) g_cpart[blockIdx.x] = make_float2(s1[0], s2[0]);
}

__global__ void k_bnsilu(const float* __restrict__ gamma, const float* __restrict__ beta) {
    int t = blockIdx.x * 256 + threadIdx.x;
    int b = t >> 12, pix = t & (NPIX - 1);
    float v[3];
    #pragma unroll
    for (int c = 0; c < 3; c++) {
        float s = 0.0f, ss = 0.0f;
        #pragma unroll
        for (int b2 = 0; b2 < NBATCH; b2++)
            #pragma unroll
            for (int ch = 0; ch < 16; ch++) {
                float2 pv = g_cpart[(b2*3 + c) * 16 + ch];
                s += pv.x; ss += pv.y;
            }
        float m   = s  * (1.0f / NSTAT);
        float var = ss * (1.0f / NSTAT) - m * m;
        float y   = g_y[(b*3 + c) * NPIX + pix];
        float n   = gamma[c] * (y - m) * rsqrtf(var + 1e-5f) + beta[c];
        v[c] = silu(n);
    }
    g_xr4[t] = make_float4(v[0], v[1], v[2], 0.0f);
}

__global__ void k_psum() {
    int gt = blockIdx.x * 256 + threadIdx.x;
    int total = gridDim.x * 256;
    for (int i = gt; i < NBATCH*3*NPIX; i += total) g_smoothed[i] = 0.0f;
    for (int i = gt; i < NBATCH*NPIX;   i += total) g_gb[i]       = 0.0f;
    if (gt < 16) g_stats[gt] = 0.0f;

    int P  = gt >> 3, xr = gt & 7;
    float s0 = 0.0f, s1 = 0.0f, s2 = 0.0f;
    if (P < NPTOT) {
        int b = P / NPP, pp = P - b * NPP;
        int hp = pp / HPN, wp = pp - hp * HPN;
        const float4* row = g_xr4 + b * NPIX + (hp + xr) * WW + wp;
        #pragma unroll
        for (int yc = 0; yc < PSZ; yc++) {
            float4 v = __ldg(row + yc);
            s0 += v.x; s1 += v.y; s2 += v.z;
        }
    }
    #pragma unroll
    for (int off = 4; off > 0; off >>= 1) {
        s0 += __shfl_down_sync(0xffffffffu, s0, off, 8);
        s1 += __shfl_down_sync(0xffffffffu, s1, off, 8);
        s2 += __shfl_down_sync(0xffffffffu, s2, off, 8);
    }
    if (xr == 0 && P < NPTOT) g_ps4[P] = make_float4(s0, s1, s2, 0.0f);
}

// Fused 5-step coordinate descent + finalize, one 64-thread block per patch.
// (u,v) accumulation basis: u = h0, v = h0*h1 (w0 = 1-u, w1 = u-v, w2 = v).
__global__ void __launch_bounds__(64, 16) k_opt() {
    int tid  = threadIdx.x;
    int wid  = tid >> 5;
    int lane = tid & 31;
    int P = blockIdx.x;
    int b = P / NPP, pp = P - b * NPP;
    int hp = pp / HPN, wpx = pp - hp * HPN;
    const float4* tile = g_xr4 + b * NPIX + hp * WW + wpx;
    float4 S = __ldg(&g_ps4[P]);

    __shared__ float sAcc[2][2][11][32];  // [parity][warp][acc][lane]
    __shared__ float sRed[2][8];

    float p[5] = {0.f, 0.f, 0.f, 0.f, 0.f};
    int q = (lane < NV) ? lane : (NV - 1);

    #pragma unroll 1
    for (int ip = 0; ip < 5; ip++) {
        float cp[5];
        #pragma unroll
        for (int j = 0; j < 5; j++) cp[j] = p[j];
        cp[ip] += cand_range(ip, q);

        Cand K = make_cand(cp);

        float acc[11];
        #pragma unroll
        for (int s = 0; s < 11; s++) acc[s] = 0.0f;

        int rbase = wid * 4;
        #pragma unroll 1
        for (int xr = 0; xr < 4; xr++) {
            int row_i = rbase + xr;
            float dy = (-1.0f + (float)row_i * (2.0f/7.0f)) - K.y0;
            float T1 = fmaf(K.A1y, dy, K.C1);
            float T3 = fmaf(K.A3y, dy, K.C3);
            float T4 = fmaf(K.A4y, dy, K.C4);
            float T2 = fmaf(K.A2y, dy, K.C2);
            const float4* row = tile + row_i * WW;
            #pragma unroll
            for (int yc = 0; yc < PSZ; yc++) {
                float cc = -1.0f + (float)yc * (2.0f/7.0f);
                float l1 = fmaf(K.A1x, cc, T1);
                float l3 = fmaf(K.A3x, cc, T3);
                float l4 = fmaf(K.A4x, cc, T4);
                float l2 = fmaf(K.A2x, cc, T2);
                float d13s = fmaf(K.sg13, fminf(l1, l3), K.off13s);
                float d42s = fmaf(K.sg42, fminf(l4, l2), K.off42s);
                float u = fast_hs(d13s);
                float h1 = fast_hs(d42s);
                float v = u * h1;
                float4 img = __ldg(row + yc);
                acc[0] += u; acc[1] += v;
                acc[2] = fmaf(img.x, u, acc[2]); acc[3] = fmaf(img.x, v, acc[3]);
                acc[4] = fmaf(img.y, u, acc[4]); acc[5] = fmaf(img.y, v, acc[5]);
                acc[6] = fmaf(img.z, u, acc[6]); acc[7] = fmaf(img.z, v, acc[7]);
                acc[8] = fmaf(u, u, acc[8]); acc[9] = fmaf(v, v, acc[9]);
                acc[10] = fmaf(u, v, acc[10]);
            }
        }

        // exchange halves (double-buffered by step parity -> one barrier/step)
        int par = ip & 1;
        #pragma unroll
        for (int s = 0; s < 11; s++) sAcc[par][wid][s][lane] = acc[s];
        __syncthreads();
        #pragma unroll
        for (int s = 0; s < 11; s++) acc[s] += sAcc[par][wid ^ 1][s][lane];

        // convert (u,v) sums to w-basis quantities (exact identities)
        float U = acc[0], V = acc[1];
        float Uu = acc[8], Vv = acc[9], Uv = acc[10];
        float sw0 = 64.0f - U;
        float sw1 = U - V;
        float sw2 = V;
        float G00 = 64.0f - 2.0f*U + Uu;
        float G11 = Uu - 2.0f*Uv + Vv;
        float G01 = U - V - Uu + Uv;
        float G02 = V - Uv;
        float G12 = Uv - Vv;
        float G22 = Vv;
        float i0 = 1.0f / (sw0 + 1e-10f);
        float i1 = 1.0f / (sw1 + 1e-10f);
        float i2 = 1.0f / (sw2 + 1e-10f);
        float Sc[3]  = {S.x, S.y, S.z};
        float Xu[3] = {acc[2], acc[4], acc[6]};
        float Xv[3] = {acc[3], acc[5], acc[7]};
        float score = 0.0f;
        #pragma unroll
        for (int c = 0; c < 3; c++) {
            float n0 = Sc[c] - Xu[c];
            float n1 = Xu[c] - Xv[c];
            float n2 = Xv[c];
            float c0 = n0*i0, c1 = n1*i1, c2 = n2*i2;
            float quad = c0*c0*G00 + c1*c1*G11 + c2*c2*G22
                       + 2.0f*(c0*c1*G01 + c0*c2*G02 + c1*c2*G12);
            score += quad - 2.0f*(c0*n0 + c1*n1 + c2*n2);
        }

        // butterfly argmin: every lane gets global best (lowest q on ties)
        float bl = score; int bq = q;
        #pragma unroll
        for (int off = 16; off > 0; off >>= 1) {
            float ol = __shfl_xor_sync(0xffffffffu, bl, off);
            int   oq = __shfl_xor_sync(0xffffffffu, bq, off);
            if (ol < bl || (ol == bl && oq < bq)) { bl = ol; bq = oq; }
        }
        p[ip] += cand_range(ip, bq);
    }

    // ---------- finalize: thread = pixel ----------
    __syncthreads();
    Cand K = make_cand(p);
    int xr = tid >> 3, yc = tid & 7;
    float dy = (-1.0f + (float)xr * (2.0f/7.0f)) - K.y0;
    float cc = -1.0f + (float)yc * (2.0f/7.0f);
    float T1 = fmaf(K.A1y, dy, K.C1);
    float T3 = fmaf(K.A3y, dy, K.C3);
    float T4 = fmaf(K.A4y, dy, K.C4);
    float T2 = fmaf(K.A2y, dy, K.C2);
    float l1 = fmaf(K.A1x, cc, T1);
    float l3 = fmaf(K.A3x, cc, T3);
    float l4 = fmaf(K.A4x, cc, T4);
    float l2 = fmaf(K.A2x, cc, T2);
    float d13s = fmaf(K.sg13, fminf(l1, l3), K.off13s);
    float d42s = fmaf(K.sg42, fminf(l4, l2), K.off42s);
    float u = fast_hs(d13s);
    float h1v = fast_hs(d42s);
    float v = u * h1v;
    float w0 = 1.0f - u, w1 = u - v, w2 = v;
    float4 img = __ldg(tile + xr * WW + yc);

    float red[8] = {u, v, img.x*u, img.x*v, img.y*u, img.y*v, img.z*u, img.z*v};
    #pragma unroll
    for (int s = 0; s < 8; s++) {
        #pragma unroll
        for (int off = 16; off > 0; off >>= 1)
            red[s] += __shfl_down_sync(0xffffffffu, red[s], off);
    }
    if (lane == 0) {
        #pragma unroll
        for (int s = 0; s < 8; s++) sRed[wid][s] = red[s];
    }
    __syncthreads();
    float tot[8];
    #pragma unroll
    for (int s = 0; s < 8; s++) tot[s] = sRed[0][s] + sRed[1][s];

    float U = tot[0], V = tot[1];
    float sw0 = 64.0f - U, sw1 = U - V, sw2 = V;
    float i0 = 1.0f / (sw0 + 1e-10f);
    float i1 = 1.0f / (sw1 + 1e-10f);
    float i2 = 1.0f / (sw2 + 1e-10f);
    float Sc[3] = {S.x, S.y, S.z};

    int opix = (xr + hp) * WW + (yc + wpx);
    #pragma unroll
    for (int c = 0; c < 3; c++) {
        float Xu = tot[2 + 2*c], Xv = tot[3 + 2*c];
        float c0 = (Sc[c] - Xu) * i0;
        float c1 = (Xu - Xv) * i1;
        float c2 = Xv * i2;
        float pv = w0*c0 + w1*c1 + w2*c2;
        atomicAdd(&g_smoothed[(b*3 + c) * NPIX + opix], pv);
    }
    float d1 = d13s, d2 = d42s;
    float mad = (d1 < 0.0f) ? -d1
              : ((d2 < 0.0f) ? fminf(d1, -d2) : fminf(d1, d2));
    float r = mad * 0.2f;   // scaled dists: mad' = 100*mad
    float lb = 1.0f / (1.0f + r * r);
    atomicAdd(&g_gb[b * NPIX + opix], lb);
}

__global__ void k_post1(const float* __restrict__ fbw, const float* __restrict__ fiw) {
    int t = blockIdx.x * 256 + threadIdx.x;
    int b = t >> 12, pix = t & (NPIX - 1);
    int h = pix >> 6, w = pix & 63;
    int ch = min(min(h + 1, HH - h), PSZ);
    int cw = min(min(w + 1, WW - w), PSZ);
    float inv = 1.0f / (float)(ch * cw);

    float sm0 = g_smoothed[(b*3 + 0) * NPIX + pix] * inv;
    float sm1 = g_smoothed[(b*3 + 1) * NPIX + pix] * inv;
    float sm2 = g_smoothed[(b*3 + 2) * NPIX + pix] * inv;
    float yi = sm0 * fiw[0] + sm1 * fiw[1] + sm2 * fiw[2];
    float gbv = g_gb[t] * inv;
    float yb = gbv * fbw[0] + gbv * fbw[1] + gbv * fbw[2];
    g_yi[t] = yi;
    g_yb[t] = yb;

    __shared__ float sA[256], sB[256];
    sA[threadIdx.x] = yb; sB[threadIdx.x] = yb * yb;
    __syncthreads();
    for (int s = 128; s > 0; s >>= 1) {
        if (threadIdx.x < s) { sA[threadIdx.x] += sA[threadIdx.x+s]; sB[threadIdx.x] += sB[threadIdx.x+s]; }
        __syncthreads();
    }
    if (threadIdx.x == 0) { atomicAdd(&g_stats[6], sA[0]); atomicAdd(&g_stats[7], sB[0]); }
    __syncthreads();
    sA[threadIdx.x] = yi; sB[threadIdx.x] = yi * yi;
    __syncthreads();
    for (int s = 128; s > 0; s >>= 1) {
        if (threadIdx.x < s) { sA[threadIdx.x] += sA[threadIdx.x+s]; sB[threadIdx.x] += sB[threadIdx.x+s]; }
        __syncthreads();
    }
    if (threadIdx.x == 0) { atomicAdd(&g_stats[8], sA[0]); atomicAdd(&g_stats[9], sB[0]); }
}

__global__ void k_out(float* __restrict__ out,
                      const float* __restrict__ fbg, const float* __restrict__ fbb,
                      const float* __restrict__ fig, const float* __restrict__ fib) {
    int t = blockIdx.x * 256 + threadIdx.x;
    float mb = g_stats[6] * (1.0f / NSTAT);
    float vb = g_stats[7] * (1.0f / NSTAT) - mb * mb;
    float nb = fbg[0] * (g_yb[t] - mb) * rsqrtf(vb + 1e-5f) + fbb[0];
    out[t] = silu(nb);

    float mi = g_stats[8] * (1.0f / NSTAT);
    float vi = g_stats[9] * (1.0f / NSTAT) - mi * mi;
    float ni = fig[0] * (g_yi[t] - mi) * rsqrtf(vi + 1e-5f) + fib[0];
    out[NBATCH * NPIX + t] = silu(ni);
}

// ---------------- launch ----------------
extern "C" void kernel_launch(void* const* d_in, const int* in_sizes, int n_in,
                              void* d_out, int out_size) {
    const float* x   = (const float*)d_in[0];
    const float* rw  = (const float*)d_in[1];
    const float* rg  = (const float*)d_in[2];
    const float* rb  = (const float*)d_in[3];
    const float* fbw = (const float*)d_in[4];
    const float* fbg = (const float*)d_in[5];
    const float* fbb = (const float*)d_in[6];
    const float* fiw = (const float*)d_in[7];
    const float* fig = (const float*)d_in[8];
    const float* fib = (const float*)d_in[9];
    float* out = (float*)d_out;

    k_conv<<<NBATCH * 3 * 16, 256>>>(x, rw);
    k_bnsilu<<<32, 256>>>(rg, rb);
    k_psum<<<(NPTOT * 8 + 255) / 256, 256>>>();
    k_opt<<<NPTOT, 64>>>();
    k_post1<<<32, 256>>>(fbw, fiw);
    k_out<<<32, 256>>>(out, fbg, fbb, fig, fib);
}

// round 10
// speedup vs baseline: 1.5646x; 1.0138x over previous
#include <cuda_runtime.h>
#include <math.h>

#define TWO_PI_F 6.28318530717958647692f
#define PI_F     3.14159265358979323846f
#define INV_PI_F 0.31830988618367094f

#define PSZ   8
#define HH    64
#define WW    64
#define HPN   57
#define NPP   (HPN*HPN)        // 3249
#define NBATCH 2
#define NPTOT (NBATCH*NPP)     // 6498
#define NV    31
#define CINN  32
#define NPIX  (HH*WW)          // 4096
#define NSTAT 8192

// ---------------- device scratch ----------------
__device__ float  g_y[NBATCH*3*NPIX];
__device__ float4 g_xr4[NBATCH*NPIX];
__device__ float  g_smoothed[NBATCH*3*NPIX];
__device__ float  g_gb[NBATCH*NPIX];
__device__ float  g_yb[NBATCH*NPIX];
__device__ float  g_yi[NBATCH*NPIX];
__device__ float  g_stats[16];
__device__ float2 g_cpart[NBATCH*3*16];

// ---------------- helpers ----------------
__device__ __forceinline__ float wrap2pi(float v) {
    v = (v >= TWO_PI_F) ? v - TWO_PI_F : v;
    v = (v < 0.0f) ? v + TWO_PI_F : v;
    return v;
}
__device__ __forceinline__ float pow35(float u) {
    float u2 = u*u, u4 = u2*u2, u8 = u4*u4, u16 = u8*u8;
    return u16*u16*u2*u;
}
__device__ __forceinline__ float silu(float v) {
    return v / (1.0f + expf(-v));
}

// h = 0.5 + atan(x)/pi, x pre-scaled by 1/eta (=100).
// PROVEN deg-9 minimax poly (R8), with 1/pi folded into the coefficients
// (exact rescale -> same decisions as R8). err(h) ~ 3e-6.
__device__ __forceinline__ float fast_hs(float x) {
    float inv;
    asm("rcp.approx.f32 %0, %1;" : "=f"(inv) : "f"(x));
    bool  big = fabsf(x) > 1.0f;
    float t = big ? inv : x;
    float s = t * t;
    float p =           0.00663216f;   //  0.0208351/pi
    p = fmaf(p, s, -0.02709664f);      // -0.0851330/pi
    p = fmaf(p, s,  0.05733850f);      //  0.1801410/pi
    p = fmaf(p, s, -0.10513345f);      // -0.3302995/pi
    p = fmaf(p, s,  0.31826723f);      //  0.9998660/pi
    float r0 = t * p;                  // atan(t)/pi
    float cs = copysignf(0.5f, x);
    float r  = big ? (cs - r0) : r0;
    return r + 0.5f;
}

// Candidate: sign+1/eta folded line coefficients, x0 folded into row constants.
struct Cand {
    float A1x,A1y,A3x,A3y,A4x,A4y,A2x,A2y;
    float C1,C3,C4,C2;
    float sg13, sg42, off13s, off42s;
    float y0;
};

__device__ __forceinline__ Cand make_cand(const float cp[5]) {
    Cand K;
    float x0 = cp[3]; K.y0 = cp[4];
    float m0 = wrap2pi(cp[0]), m1 = wrap2pi(cp[1]), m2 = wrap2pi(cp[2]);
    float lo = fminf(m0, m1), hi = fmaxf(m0, m1);
    float a1 = fminf(lo, m2);
    float a3 = fmaxf(hi, m2);
    float a2 = fmaxf(lo, fminf(hi, m2));
    float a4 = 0.5f*(a1 + a3) + ((a3 > a1) ? PI_F : 0.0f);
    float d13 = a3 - a1;
    float m   = a2 - a4;
    float d42 = (m < 0.0f) ? m + TWO_PI_F : m;
    K.sg13 = (d13 < PI_F) ? 1.0f : -1.0f;
    K.sg42 = (d42 < PI_F) ? 1.0f : -1.0f;
    K.off13s = 10.0f * pow35(d13 * INV_PI_F - 1.0f);
    K.off42s = 10.0f * pow35(d42 * INV_PI_F - 1.0f);
    float s1,c1,s2,c2,s3,c3,s4,c4;
    __sincosf(a1, &s1, &c1);
    __sincosf(a2, &s2, &c2);
    __sincosf(a3, &s3, &c3);
    __sincosf(a4, &s4, &c4);
    float f13 = 100.0f * K.sg13, f42 = 100.0f * K.sg42;
    K.A1x = -f13 * s1;  K.A1y =  f13 * c1;
    K.A3x =  f13 * s3;  K.A3y = -f13 * c3;
    K.A4x = -f42 * s4;  K.A4y =  f42 * c4;
    K.A2x =  f42 * s2;  K.A2y = -f42 * c2;
    K.C1 = -K.A1x * x0; K.C3 = -K.A3x * x0;
    K.C4 = -K.A4x * x0; K.C2 = -K.A2x * x0;
    return K;
}

__device__ __forceinline__ float cand_range(int ip, int q) {
    return (ip < 3) ? (float)q * (TWO_PI_F / 31.0f)
                    : (-3.0f + (float)q * 0.2f);
}

// ---------------- kernels ----------------
__global__ void k_conv(const float* __restrict__ x, const float* __restrict__ rw) {
    int gt = blockIdx.x * 256 + threadIdx.x;   // 0..24575
    // fused zero-fill of fold buffers / stats (consumed after k_opt)
    g_smoothed[gt] = 0.0f;
    if (gt < NBATCH*NPIX) g_gb[gt] = 0.0f;
    if (gt < 16) g_stats[gt] = 0.0f;

    int bo = blockIdx.x >> 4;
    int chunk = blockIdx.x & 15;
    int b = bo / 3, o = bo % 3;
    int pix = chunk * 256 + threadIdx.x;
    const float* xp = x + (size_t)b * CINN * NPIX + pix;
    float acc = 0.0f;
    #pragma unroll
    for (int c = 0; c < CINN; c++)
        acc = fmaf(xp[c * NPIX], rw[o * CINN + c], acc);
    g_y[(b*3 + o) * NPIX + pix] = acc;

    __shared__ float s1[256], s2[256];
    s1[threadIdx.x] = acc; s2[threadIdx.x] = acc * acc;
    __syncthreads();
    for (int s = 128; s > 0; s >>= 1) {
        if (threadIdx.x < s) { s1[threadIdx.x] += s1[threadIdx.x+s]; s2[threadIdx.x] += s2[threadIdx.x+s]; }
        __syncthreads();
    }
    if (threadIdx.x == 0) g_cpart[blockIdx.x] = make_float2(s1[0], s2[0]);
}

__global__ void k_bnsilu(const float* __restrict__ gamma, const float* __restrict__ beta) {
    int t = blockIdx.x * 256 + threadIdx.x;
    int b = t >> 12, pix = t & (NPIX - 1);
    float v[3];
    #pragma unroll
    for (int c = 0; c < 3; c++) {
        float s = 0.0f, ss = 0.0f;
        #pragma unroll
        for (int b2 = 0; b2 < NBATCH; b2++)
            #pragma unroll
            for (int ch = 0; ch < 16; ch++) {
                float2 pv = g_cpart[(b2*3 + c) * 16 + ch];
                s += pv.x; ss += pv.y;
            }
        float m   = s  * (1.0f / NSTAT);
        float var = ss * (1.0f / NSTAT) - m * m;
        float y   = g_y[(b*3 + c) * NPIX + pix];
        float n   = gamma[c] * (y - m) * rsqrtf(var + 1e-5f) + beta[c];
        v[c] = silu(n);
    }
    g_xr4[t] = make_float4(v[0], v[1], v[2], 0.0f);
}

// Fused: per-patch channel sums + 5-step coordinate descent + finalize.
// One 64-thread block per patch; steps: 2 warps x half-patch, lane = candidate.
__global__ void __launch_bounds__(64, 16) k_opt() {
    int tid  = threadIdx.x;
    int wid  = tid >> 5;
    int lane = tid & 31;
    int P = blockIdx.x;
    int b = P / NPP, pp = P - b * NPP;
    int hp = pp / HPN, wpx = pp - hp * HPN;
    const float4* tile = g_xr4 + b * NPIX + hp * WW + wpx;

    __shared__ float sAcc[2][2][11][32];  // [parity][warp][acc][lane]
    __shared__ float sRed[2][8];

    // ---------- prologue: per-patch channel sums (thread = pixel) ----------
    int fxr = tid >> 3, fyc = tid & 7;
    {
        float4 fimg = __ldg(tile + fxr * WW + fyc);
        float t0 = fimg.x, t1 = fimg.y, t2 = fimg.z;
        #pragma unroll
        for (int off = 16; off > 0; off >>= 1) {
            t0 += __shfl_down_sync(0xffffffffu, t0, off);
            t1 += __shfl_down_sync(0xffffffffu, t1, off);
            t2 += __shfl_down_sync(0xffffffffu, t2, off);
        }
        if (lane == 0) { sRed[wid][0] = t0; sRed[wid][1] = t1; sRed[wid][2] = t2; }
    }
    __syncthreads();
    float4 S = make_float4(sRed[0][0] + sRed[1][0],
                           sRed[0][1] + sRed[1][1],
                           sRed[0][2] + sRed[1][2], 0.0f);

    float p[5] = {0.f, 0.f, 0.f, 0.f, 0.f};
    int q = (lane < NV) ? lane : (NV - 1);

    #pragma unroll 1
    for (int ip = 0; ip < 5; ip++) {
        float cp[5];
        #pragma unroll
        for (int j = 0; j < 5; j++) cp[j] = p[j];
        cp[ip] += cand_range(ip, q);

        Cand K = make_cand(cp);

        float acc[11];
        #pragma unroll
        for (int s = 0; s < 11; s++) acc[s] = 0.0f;

        int rbase = wid * 4;
        #pragma unroll 1
        for (int xr = 0; xr < 4; xr++) {
            int row_i = rbase + xr;
            float dy = (-1.0f + (float)row_i * (2.0f/7.0f)) - K.y0;
            float T1 = fmaf(K.A1y, dy, K.C1);
            float T3 = fmaf(K.A3y, dy, K.C3);
            float T4 = fmaf(K.A4y, dy, K.C4);
            float T2 = fmaf(K.A2y, dy, K.C2);
            const float4* row = tile + row_i * WW;
            #pragma unroll
            for (int yc = 0; yc < PSZ; yc++) {
                float cc = -1.0f + (float)yc * (2.0f/7.0f);
                float l1 = fmaf(K.A1x, cc, T1);
                float l3 = fmaf(K.A3x, cc, T3);
                float l4 = fmaf(K.A4x, cc, T4);
                float l2 = fmaf(K.A2x, cc, T2);
                float d13s = fmaf(K.sg13, fminf(l1, l3), K.off13s);
                float d42s = fmaf(K.sg42, fminf(l4, l2), K.off42s);
                float u = fast_hs(d13s);
                float h1 = fast_hs(d42s);
                float v = u * h1;
                float4 img = __ldg(row + yc);
                acc[0] += u; acc[1] += v;
                acc[2] = fmaf(img.x, u, acc[2]); acc[3] = fmaf(img.x, v, acc[3]);
                acc[4] = fmaf(img.y, u, acc[4]); acc[5] = fmaf(img.y, v, acc[5]);
                acc[6] = fmaf(img.z, u, acc[6]); acc[7] = fmaf(img.z, v, acc[7]);
                acc[8] = fmaf(u, u, acc[8]); acc[9] = fmaf(v, v, acc[9]);
                acc[10] = fmaf(u, v, acc[10]);
            }
        }

        // exchange halves (double-buffered by step parity -> one barrier/step)
        int par = ip & 1;
        #pragma unroll
        for (int s = 0; s < 11; s++) sAcc[par][wid][s][lane] = acc[s];
        __syncthreads();
        #pragma unroll
        for (int s = 0; s < 11; s++) acc[s] += sAcc[par][wid ^ 1][s][lane];

        // convert (u,v) sums to w-basis quantities (exact identities)
        float U = acc[0], V = acc[1];
        float Uu = acc[8], Vv = acc[9], Uv = acc[10];
        float sw0 = 64.0f - U;
        float sw1 = U - V;
        float sw2 = V;
        float G00 = 64.0f - 2.0f*U + Uu;
        float G11 = Uu - 2.0f*Uv + Vv;
        float G01 = U - V - Uu + Uv;
        float G02 = V - Uv;
        float G12 = Uv - Vv;
        float G22 = Vv;
        float i0 = 1.0f / (sw0 + 1e-10f);
        float i1 = 1.0f / (sw1 + 1e-10f);
        float i2 = 1.0f / (sw2 + 1e-10f);
        float Sc[3]  = {S.x, S.y, S.z};
        float Xu[3] = {acc[2], acc[4], acc[6]};
        float Xv[3] = {acc[3], acc[5], acc[7]};
        float score = 0.0f;
        #pragma unroll
        for (int c = 0; c < 3; c++) {
            float n0 = Sc[c] - Xu[c];
            float n1 = Xu[c] - Xv[c];
            float n2 = Xv[c];
            float c0 = n0*i0, c1 = n1*i1, c2 = n2*i2;
            float quad = c0*c0*G00 + c1*c1*G11 + c2*c2*G22
                       + 2.0f*(c0*c1*G01 + c0*c2*G02 + c1*c2*G12);
            score += quad - 2.0f*(c0*n0 + c1*n1 + c2*n2);
        }

        // butterfly argmin: every lane gets global best (lowest q on ties)
        float bl = score; int bq = q;
        #pragma unroll
        for (int off = 16; off > 0; off >>= 1) {
            float ol = __shfl_xor_sync(0xffffffffu, bl, off);
            int   oq = __shfl_xor_sync(0xffffffffu, bq, off);
            if (ol < bl || (ol == bl && oq < bq)) { bl = ol; bq = oq; }
        }
        p[ip] += cand_range(ip, bq);
    }

    // ---------- finalize: thread = pixel ----------
    Cand K = make_cand(p);
    float dy = (-1.0f + (float)fxr * (2.0f/7.0f)) - K.y0;
    float cc = -1.0f + (float)fyc * (2.0f/7.0f);
    float T1 = fmaf(K.A1y, dy, K.C1);
    float T3 = fmaf(K.A3y, dy, K.C3);
    float T4 = fmaf(K.A4y, dy, K.C4);
    float T2 = fmaf(K.A2y, dy, K.C2);
    float l1 = fmaf(K.A1x, cc, T1);
    float l3 = fmaf(K.A3x, cc, T3);
    float l4 = fmaf(K.A4x, cc, T4);
    float l2 = fmaf(K.A2x, cc, T2);
    float d13s = fmaf(K.sg13, fminf(l1, l3), K.off13s);
    float d42s = fmaf(K.sg42, fminf(l4, l2), K.off42s);
    float u = fast_hs(d13s);
    float h1v = fast_hs(d42s);
    float v = u * h1v;
    float w0 = 1.0f - u, w1 = u - v, w2 = v;
    float4 img = __ldg(tile + fxr * WW + fyc);

    float red[8] = {u, v, img.x*u, img.x*v, img.y*u, img.y*v, img.z*u, img.z*v};
    #pragma unroll
    for (int s = 0; s < 8; s++) {
        #pragma unroll
        for (int off = 16; off > 0; off >>= 1)
            red[s] += __shfl_down_sync(0xffffffffu, red[s], off);
    }
    if (lane == 0) {
        #pragma unroll
        for (int s = 0; s < 8; s++) sRed[wid][s] = red[s];
    }
    __syncthreads();
    float tot[8];
    #pragma unroll
    for (int s = 0; s < 8; s++) tot[s] = sRed[0][s] + sRed[1][s];

    float U = tot[0], V = tot[1];
    float sw0 = 64.0f - U, sw1 = U - V, sw2 = V;
    float i0 = 1.0f / (sw0 + 1e-10f);
    float i1 = 1.0f / (sw1 + 1e-10f);
    float i2 = 1.0f / (sw2 + 1e-10f);
    float Sc[3] = {S.x, S.y, S.z};

    int opix = (fxr + hp) * WW + (fyc + wpx);
    #pragma unroll
    for (int c = 0; c < 3; c++) {
        float Xu = tot[2 + 2*c], Xv = tot[3 + 2*c];
        float c0 = (Sc[c] - Xu) * i0;
        float c1 = (Xu - Xv) * i1;
        float c2 = Xv * i2;
        float pv = w0*c0 + w1*c1 + w2*c2;
        atomicAdd(&g_smoothed[(b*3 + c) * NPIX + opix], pv);
    }
    float d1 = d13s, d2 = d42s;
    float mad = (d1 < 0.0f) ? -d1
              : ((d2 < 0.0f) ? fminf(d1, -d2) : fminf(d1, d2));
    float r = mad * 0.2f;   // scaled dists: mad' = 100*mad
    float lb = 1.0f / (1.0f + r * r);
    atomicAdd(&g_gb[b * NPIX + opix], lb);
}

__global__ void k_post1(const float* __restrict__ fbw, const float* __restrict__ fiw) {
    int t = blockIdx.x * 256 + threadIdx.x;
    int b = t >> 12, pix = t & (NPIX - 1);
    int h = pix >> 6, w = pix & 63;
    int ch = min(min(h + 1, HH - h), PSZ);
    int cw = min(min(w + 1, WW - w), PSZ);
    float inv = 1.0f / (float)(ch * cw);

    float sm0 = g_smoothed[(b*3 + 0) * NPIX + pix] * inv;
    float sm1 = g_smoothed[(b*3 + 1) * NPIX + pix] * inv;
    float sm2 = g_smoothed[(b*3 + 2) * NPIX + pix] * inv;
    float yi = sm0 * fiw[0] + sm1 * fiw[1] + sm2 * fiw[2];
    float gbv = g_gb[t] * inv;
    float yb = gbv * fbw[0] + gbv * fbw[1] + gbv * fbw[2];
    g_yi[t] = yi;
    g_yb[t] = yb;

    __shared__ float sA[256], sB[256];
    sA[threadIdx.x] = yb; sB[threadIdx.x] = yb * yb;
    __syncthreads();
    for (int s = 128; s > 0; s >>= 1) {
        if (threadIdx.x < s) { sA[threadIdx.x] += sA[threadIdx.x+s]; sB[threadIdx.x] += sB[threadIdx.x+s]; }
        __syncthreads();
    }
    if (threadIdx.x == 0) { atomicAdd(&g_stats[6], sA[0]); atomicAdd(&g_stats[7], sB[0]); }
    __syncthreads();
    sA[threadIdx.x] = yi; sB[threadIdx.x] = yi * yi;
    __syncthreads();
    for (int s = 128; s > 0; s >>= 1) {
        if (threadIdx.x < s) { sA[threadIdx.x] += sA[threadIdx.x+s]; sB[threadIdx.x] += sB[threadIdx.x+s]; }
        __syncthreads();
    }
    if (threadIdx.x == 0) { atomicAdd(&g_stats[8], sA[0]); atomicAdd(&g_stats[9], sB[0]); }
}

__global__ void k_out(float* __restrict__ out,
                      const float* __restrict__ fbg, const float* __restrict__ fbb,
                      const float* __restrict__ fig, const float* __restrict__ fib) {
    int t = blockIdx.x * 256 + threadIdx.x;
    float mb = g_stats[6] * (1.0f / NSTAT);
    float vb = g_stats[7] * (1.0f / NSTAT) - mb * mb;
    float nb = fbg[0] * (g_yb[t] - mb) * rsqrtf(vb + 1e-5f) + fbb[0];
    out[t] = silu(nb);

    float mi = g_stats[8] * (1.0f / NSTAT);
    float vi = g_stats[9] * (1.0f / NSTAT) - mi * mi;
    float ni = fig[0] * (g_yi[t] - mi) * rsqrtf(vi + 1e-5f) + fib[0];
    out[NBATCH * NPIX + t] = silu(ni);
}

// ---------------- launch ----------------
extern "C" void kernel_launch(void* const* d_in, const int* in_sizes, int n_in,
                              void* d_out, int out_size) {
    const float* x   = (const float*)d_in[0];
    const float* rw  = (const float*)d_in[1];
    const float* rg  = (const float*)d_in[2];
    const float* rb  = (const float*)d_in[3];
    const float* fbw = (const float*)d_in[4];
    const float* fbg = (const float*)d_in[5];
    const float* fbb = (const float*)d_in[6];
    const float* fiw = (const float*)d_in[7];
    const float* fig = (const float*)d_in[8];
    const float* fib = (const float*)d_in[9];
    float* out = (float*)d_out;

    k_conv<<<NBATCH * 3 * 16, 256>>>(x, rw);
    k_bnsilu<<<32, 256>>>(rg, rb);
    k_opt<<<NPTOT, 64>>>();
    k_post1<<<32, 256>>>(fbw, fiw);
    k_out<<<32, 256>>>(out, fbg, fbb, fig, fib);
}

// round 12
// speedup vs baseline: 1.6028x; 1.0244x over previous
#include <cuda_runtime.h>
#include <math.h>

#define TWO_PI_F 6.28318530717958647692f
#define PI_F     3.14159265358979323846f
#define INV_PI_F 0.31830988618367094f

#define PSZ   8
#define HH    64
#define WW    64
#define HPN   57
#define NPP   (HPN*HPN)        // 3249
#define NBATCH 2
#define NPTOT (NBATCH*NPP)     // 6498
#define NV    31
#define CINN  32
#define NPIX  (HH*WW)          // 4096
#define NSTAT 8192

// ---------------- device scratch ----------------
__device__ float  g_y[NBATCH*3*NPIX];
__device__ float4 g_xr4[NBATCH*NPIX];
__device__ float  g_smoothed[NBATCH*3*NPIX];
__device__ float  g_gb[NBATCH*NPIX];
__device__ float  g_yb[NBATCH*NPIX];
__device__ float  g_yi[NBATCH*NPIX];
__device__ float  g_stats[16];
__device__ float2 g_cpart[NBATCH*3*16];

// ---------------- packed f32x2 helpers ----------------
typedef unsigned long long f2;
__device__ __forceinline__ f2 pk(float lo, float hi) {
    f2 r; asm("mov.b64 %0,{%1,%2};" : "=l"(r) : "f"(lo), "f"(hi)); return r;
}
__device__ __forceinline__ f2 pk2(float c) { return pk(c, c); }
__device__ __forceinline__ void upk(f2 v, float& lo, float& hi) {
    asm("mov.b64 {%0,%1},%2;" : "=f"(lo), "=f"(hi) : "l"(v));
}
__device__ __forceinline__ f2 fma2(f2 a, f2 b, f2 c) {
    f2 r; asm("fma.rn.f32x2 %0,%1,%2,%3;" : "=l"(r) : "l"(a), "l"(b), "l"(c)); return r;
}
__device__ __forceinline__ f2 mul2(f2 a, f2 b) {
    f2 r; asm("mul.rn.f32x2 %0,%1,%2;" : "=l"(r) : "l"(a), "l"(b)); return r;
}

// ---------------- helpers ----------------
__device__ __forceinline__ float wrap2pi(float v) {
    v = (v >= TWO_PI_F) ? v - TWO_PI_F : v;
    v = (v < 0.0f) ? v + TWO_PI_F : v;
    return v;
}
__device__ __forceinline__ float pow35(float u) {
    float u2 = u*u, u4 = u2*u2, u8 = u4*u4, u16 = u8*u8;
    return u16*u16*u2*u;
}
__device__ __forceinline__ float silu(float v) {
    return v / (1.0f + expf(-v));
}

// Paired h = 0.5 + atan(x)/pi (x pre-scaled by 1/eta=100).
// Polynomial section in packed f32x2; per-lane bit-identical to the proven
// R10 deg-9 scalar poly (1/pi folded). err(h) ~ 3e-6.
__device__ __forceinline__ void fast_hs2(float xa, float xb,
                                         f2 C4, f2 C3, f2 C2, f2 C1, f2 C0,
                                         float& ha, float& hb) {
    float ia, ib;
    asm("rcp.approx.f32 %0, %1;" : "=f"(ia) : "f"(xa));
    asm("rcp.approx.f32 %0, %1;" : "=f"(ib) : "f"(xb));
    bool ba = fabsf(xa) > 1.0f;
    bool bb = fabsf(xb) > 1.0f;
    float ta = ba ? ia : xa;
    float tb = bb ? ib : xb;
    f2 t = pk(ta, tb);
    f2 s = mul2(t, t);
    f2 p = fma2(C4, s, C3);
    p = fma2(p, s, C2);
    p = fma2(p, s, C1);
    p = fma2(p, s, C0);
    f2 r0 = mul2(t, p);
    float ra, rb; upk(r0, ra, rb);
    float fa = ba ? (copysignf(0.5f, xa) - ra) : ra;
    float fb = bb ? (copysignf(0.5f, xb) - rb) : rb;
    ha = fa + 0.5f;
    hb = fb + 0.5f;
}

// Candidate: 1/eta folded, SIGN-FREE line coefficients (sg handled by
// predicate min/max):  M1 = 100*line(a1), M3 = -100*line(a3)
//   d13s = (sg13>0 ? min(M1,M3) : max(M1,M3)) + off13s   [exact identity]
struct Cand {
    float A1x,A1y,A3x,A3y,A4x,A4y,A2x,A2y;
    float C1,C3,C4,C2;
    float off13s, off42s;
    float y0;
    bool  min13, min42;
};

__device__ __forceinline__ Cand make_cand(const float cp[5]) {
    Cand K;
    float x0 = cp[3]; K.y0 = cp[4];
    float m0 = wrap2pi(cp[0]), m1 = wrap2pi(cp[1]), m2 = wrap2pi(cp[2]);
    float lo = fminf(m0, m1), hi = fmaxf(m0, m1);
    float a1 = fminf(lo, m2);
    float a3 = fmaxf(hi, m2);
    float a2 = fmaxf(lo, fminf(hi, m2));
    float a4 = 0.5f*(a1 + a3) + ((a3 > a1) ? PI_F : 0.0f);
    float d13 = a3 - a1;
    float m   = a2 - a4;
    float d42 = (m < 0.0f) ? m + TWO_PI_F : m;
    K.min13 = (d13 < PI_F);
    K.min42 = (d42 < PI_F);
    K.off13s = 10.0f * pow35(d13 * INV_PI_F - 1.0f);
    K.off42s = 10.0f * pow35(d42 * INV_PI_F - 1.0f);
    float s1,c1,s2,c2,s3,c3,s4,c4;
    __sincosf(a1, &s1, &c1);
    __sincosf(a2, &s2, &c2);
    __sincosf(a3, &s3, &c3);
    __sincosf(a4, &s4, &c4);
    const float f = 100.0f;              // SIGN-FREE (bug fix vs R11)
    K.A1x = -f * s1;  K.A1y =  f * c1;
    K.A3x =  f * s3;  K.A3y = -f * c3;
    K.A4x = -f * s4;  K.A4y =  f * c4;
    K.A2x =  f * s2;  K.A2y = -f * c2;
    K.C1 = -K.A1x * x0; K.C3 = -K.A3x * x0;
    K.C4 = -K.A4x * x0; K.C2 = -K.A2x * x0;
    return K;
}

__device__ __forceinline__ float cand_range(int ip, int q) {
    return (ip < 3) ? (float)q * (TWO_PI_F / 31.0f)
                    : (-3.0f + (float)q * 0.2f);
}

// ---------------- kernels ----------------
__global__ void k_conv(const float* __restrict__ x, const float* __restrict__ rw) {
    int gt = blockIdx.x * 256 + threadIdx.x;   // 0..24575
    g_smoothed[gt] = 0.0f;
    if (gt < NBATCH*NPIX) g_gb[gt] = 0.0f;
    if (gt < 16) g_stats[gt] = 0.0f;

    int bo = blockIdx.x >> 4;
    int chunk = blockIdx.x & 15;
    int b = bo / 3, o = bo % 3;
    int pix = chunk * 256 + threadIdx.x;
    const float* xp = x + (size_t)b * CINN * NPIX + pix;
    float acc = 0.0f;
    #pragma unroll
    for (int c = 0; c < CINN; c++)
        acc = fmaf(xp[c * NPIX], rw[o * CINN + c], acc);
    g_y[(b*3 + o) * NPIX + pix] = acc;

    __shared__ float s1[256], s2[256];
    s1[threadIdx.x] = acc; s2[threadIdx.x] = acc * acc;
    __syncthreads();
    for (int s = 128; s > 0; s >>= 1) {
        if (threadIdx.x < s) { s1[threadIdx.x] += s1[threadIdx.x+s]; s2[threadIdx.x] += s2[threadIdx.x+s]; }
        __syncthreads();
    }
    if (threadIdx.x == 0) g_cpart[blockIdx.x] = make_float2(s1[0], s2[0]);
}

__global__ void k_bnsilu(const float* __restrict__ gamma, const float* __restrict__ beta) {
    int t = blockIdx.x * 256 + threadIdx.x;
    int b = t >> 12, pix = t & (NPIX - 1);
    float v[3];
    #pragma unroll
    for (int c = 0; c < 3; c++) {
        float s = 0.0f, ss = 0.0f;
        #pragma unroll
        for (int b2 = 0; b2 < NBATCH; b2++)
            #pragma unroll
            for (int ch = 0; ch < 16; ch++) {
                float2 pv = g_cpart[(b2*3 + c) * 16 + ch];
                s += pv.x; ss += pv.y;
            }
        float m   = s  * (1.0f / NSTAT);
        float var = ss * (1.0f / NSTAT) - m * m;
        float y   = g_y[(b*3 + c) * NPIX + pix];
        float n   = gamma[c] * (y - m) * rsqrtf(var + 1e-5f) + beta[c];
        v[c] = silu(n);
    }
    g_xr4[t] = make_float4(v[0], v[1], v[2], 0.0f);
}

// Fused: per-patch channel sums + 5-step coordinate descent + finalize.
__global__ void __launch_bounds__(64, 16) k_opt() {
    int tid  = threadIdx.x;
    int wid  = tid >> 5;
    int lane = tid & 31;
    int P = blockIdx.x;
    int b = P / NPP, pp = P - b * NPP;
    int hp = pp / HPN, wpx = pp - hp * HPN;
    const float4* tile = g_xr4 + b * NPIX + hp * WW + wpx;

    __shared__ float sAcc[2][2][11][32];  // [parity][warp][acc][lane]
    __shared__ float sRed[2][8];

    // packed poly constants (loop-invariant; lanes identical)
    const f2 PC4 = pk2( 0.00663216f);
    const f2 PC3 = pk2(-0.02709664f);
    const f2 PC2 = pk2( 0.05733850f);
    const f2 PC1 = pk2(-0.10513345f);
    const f2 PC0 = pk2( 0.31826723f);

    // ---------- prologue: per-patch channel sums (thread = pixel) ----------
    int fxr = tid >> 3, fyc = tid & 7;
    {
        float4 fimg = __ldg(tile + fxr * WW + fyc);
        float t0 = fimg.x, t1 = fimg.y, t2 = fimg.z;
        #pragma unroll
        for (int off = 16; off > 0; off >>= 1) {
            t0 += __shfl_down_sync(0xffffffffu, t0, off);
            t1 += __shfl_down_sync(0xffffffffu, t1, off);
            t2 += __shfl_down_sync(0xffffffffu, t2, off);
        }
        if (lane == 0) { sRed[wid][0] = t0; sRed[wid][1] = t1; sRed[wid][2] = t2; }
    }
    __syncthreads();
    float4 S = make_float4(sRed[0][0] + sRed[1][0],
                           sRed[0][1] + sRed[1][1],
                           sRed[0][2] + sRed[1][2], 0.0f);

    float p[5] = {0.f, 0.f, 0.f, 0.f, 0.f};
    int q = (lane < NV) ? lane : (NV - 1);

    #pragma unroll 1
    for (int ip = 0; ip < 5; ip++) {
        float cp[5];
        #pragma unroll
        for (int j = 0; j < 5; j++) cp[j] = p[j];
        cp[ip] += cand_range(ip, q);

        Cand K = make_cand(cp);

        float acc[11];
        #pragma unroll
        for (int s = 0; s < 11; s++) acc[s] = 0.0f;

        int rbase = wid * 4;
        #pragma unroll 1
        for (int xr = 0; xr < 4; xr++) {
            int row_i = rbase + xr;
            float dy = (-1.0f + (float)row_i * (2.0f/7.0f)) - K.y0;
            float T1 = fmaf(K.A1y, dy, K.C1);
            float T3 = fmaf(K.A3y, dy, K.C3);
            float T4 = fmaf(K.A4y, dy, K.C4);
            float T2 = fmaf(K.A2y, dy, K.C2);
            const float4* row = tile + row_i * WW;
            #pragma unroll
            for (int yc = 0; yc < PSZ; yc++) {
                float cc = -1.0f + (float)yc * (2.0f/7.0f);
                float l1 = fmaf(K.A1x, cc, T1);
                float l3 = fmaf(K.A3x, cc, T3);
                float l4 = fmaf(K.A4x, cc, T4);
                float l2 = fmaf(K.A2x, cc, T2);
                float m13 = K.min13 ? fminf(l1, l3) : fmaxf(l1, l3);
                float m42 = K.min42 ? fminf(l4, l2) : fmaxf(l4, l2);
                float d13s = m13 + K.off13s;
                float d42s = m42 + K.off42s;
                float u, h1;
                fast_hs2(d13s, d42s, PC4, PC3, PC2, PC1, PC0, u, h1);
                float v = u * h1;
                float4 img = __ldg(row + yc);
                acc[0] += u; acc[1] += v;
                acc[2] = fmaf(img.x, u, acc[2]); acc[3] = fmaf(img.x, v, acc[3]);
                acc[4] = fmaf(img.y, u, acc[4]); acc[5] = fmaf(img.y, v, acc[5]);
                acc[6] = fmaf(img.z, u, acc[6]); acc[7] = fmaf(img.z, v, acc[7]);
                acc[8] = fmaf(u, u, acc[8]); acc[9] = fmaf(v, v, acc[9]);
                acc[10] = fmaf(u, v, acc[10]);
            }
        }

        // exchange halves (double-buffered by step parity -> one barrier/step)
        int par = ip & 1;
        #pragma unroll
        for (int s = 0; s < 11; s++) sAcc[par][wid][s][lane] = acc[s];
        __syncthreads();
        #pragma unroll
        for (int s = 0; s < 11; s++) acc[s] += sAcc[par][wid ^ 1][s][lane];

        // convert (u,v) sums to w-basis quantities (exact identities)
        float U = acc[0], V = acc[1];
        float Uu = acc[8], Vv = acc[9], Uv = acc[10];
        float sw0 = 64.0f - U;
        float sw1 = U - V;
        float sw2 = V;
        float G00 = 64.0f - 2.0f*U + Uu;
        float G11 = Uu - 2.0f*Uv + Vv;
        float G01 = U - V - Uu + Uv;
        float G02 = V - Uv;
        float G12 = Uv - Vv;
        float G22 = Vv;
        float i0 = 1.0f / (sw0 + 1e-10f);
        float i1 = 1.0f / (sw1 + 1e-10f);
        float i2 = 1.0f / (sw2 + 1e-10f);
        float Sc[3]  = {S.x, S.y, S.z};
        float Xu[3] = {acc[2], acc[4], acc[6]};
        float Xv[3] = {acc[3], acc[5], acc[7]};
        float score = 0.0f;
        #pragma unroll
        for (int c = 0; c < 3; c++) {
            float n0 = Sc[c] - Xu[c];
            float n1 = Xu[c] - Xv[c];
            float n2 = Xv[c];
            float c0 = n0*i0, c1 = n1*i1, c2 = n2*i2;
            float quad = c0*c0*G00 + c1*c1*G11 + c2*c2*G22
                       + 2.0f*(c0*c1*G01 + c0*c2*G02 + c1*c2*G12);
            score += quad - 2.0f*(c0*n0 + c1*n1 + c2*n2);
        }

        // butterfly argmin: every lane gets global best (lowest q on ties)
        float bl = score; int bq = q;
        #pragma unroll
        for (int off = 16; off > 0; off >>= 1) {
            float ol = __shfl_xor_sync(0xffffffffu, bl, off);
            int   oq = __shfl_xor_sync(0xffffffffu, bq, off);
            if (ol < bl || (ol == bl && oq < bq)) { bl = ol; bq = oq; }
        }
        p[ip] += cand_range(ip, bq);
    }

    // ---------- finalize: thread = pixel ----------
    Cand K = make_cand(p);
    float dy = (-1.0f + (float)fxr * (2.0f/7.0f)) - K.y0;
    float cc = -1.0f + (float)fyc * (2.0f/7.0f);
    float T1 = fmaf(K.A1y, dy, K.C1);
    float T3 = fmaf(K.A3y, dy, K.C3);
    float T4 = fmaf(K.A4y, dy, K.C4);
    float T2 = fmaf(K.A2y, dy, K.C2);
    float l1 = fmaf(K.A1x, cc, T1);
    float l3 = fmaf(K.A3x, cc, T3);
    float l4 = fmaf(K.A4x, cc, T4);
    float l2 = fmaf(K.A2x, cc, T2);
    float m13 = K.min13 ? fminf(l1, l3) : fmaxf(l1, l3);
    float m42 = K.min42 ? fminf(l4, l2) : fmaxf(l4, l2);
    float d13s = m13 + K.off13s;
    float d42s = m42 + K.off42s;
    float u, h1v;
    fast_hs2(d13s, d42s, PC4, PC3, PC2, PC1, PC0, u, h1v);
    float v = u * h1v;
    float w0 = 1.0f - u, w1 = u - v, w2 = v;
    float4 img = __ldg(tile + fxr * WW + fyc);

    float red[8] = {u, v, img.x*u, img.x*v, img.y*u, img.y*v, img.z*u, img.z*v};
    #pragma unroll
    for (int s = 0; s < 8; s++) {
        #pragma unroll
        for (int off = 16; off > 0; off >>= 1)
            red[s] += __shfl_down_sync(0xffffffffu, red[s], off);
    }
    if (lane == 0) {
        #pragma unroll
        for (int s = 0; s < 8; s++) sRed[wid][s] = red[s];
    }
    __syncthreads();
    float tot[8];
    #pragma unroll
    for (int s = 0; s < 8; s++) tot[s] = sRed[0][s] + sRed[1][s];

    float U = tot[0], V = tot[1];
    float sw0 = 64.0f - U, sw1 = U - V, sw2 = V;
    float i0 = 1.0f / (sw0 + 1e-10f);
    float i1 = 1.0f / (sw1 + 1e-10f);
    float i2 = 1.0f / (sw2 + 1e-10f);
    float Sc[3] = {S.x, S.y, S.z};

    int opix = (fxr + hp) * WW + (fyc + wpx);
    #pragma unroll
    for (int c = 0; c < 3; c++) {
        float Xu = tot[2 + 2*c], Xv = tot[3 + 2*c];
        float c0 = (Sc[c] - Xu) * i0;
        float c1 = (Xu - Xv) * i1;
        float c2 = Xv * i2;
        float pv = w0*c0 + w1*c1 + w2*c2;
        atomicAdd(&g_smoothed[(b*3 + c) * NPIX + opix], pv);
    }
    float d1 = d13s, d2 = d42s;
    float mad = (d1 < 0.0f) ? -d1
              : ((d2 < 0.0f) ? fminf(d1, -d2) : fminf(d1, d2));
    float r = mad * 0.2f;   // scaled dists: mad' = 100*mad
    float lb = 1.0f / (1.0f + r * r);
    atomicAdd(&g_gb[b * NPIX + opix], lb);
}

__global__ void k_post1(const float* __restrict__ fbw, const float* __restrict__ fiw) {
    int t = blockIdx.x * 256 + threadIdx.x;
    int b = t >> 12, pix = t & (NPIX - 1);
    int h = pix >> 6, w = pix & 63;
    int ch = min(min(h + 1, HH - h), PSZ);
    int cw = min(min(w + 1, WW - w), PSZ);
    float inv = 1.0f / (float)(ch * cw);

    float sm0 = g_smoothed[(b*3 + 0) * NPIX + pix] * inv;
    float sm1 = g_smoothed[(b*3 + 1) * NPIX + pix] * inv;
    float sm2 = g_smoothed[(b*3 + 2) * NPIX + pix] * inv;
    float yi = sm0 * fiw[0] + sm1 * fiw[1] + sm2 * fiw[2];
    float gbv = g_gb[t] * inv;
    float yb = gbv * fbw[0] + gbv * fbw[1] + gbv * fbw[2];
    g_yi[t] = yi;
    g_yb[t] = yb;

    __shared__ float sA[256], sB[256];
    sA[threadIdx.x] = yb; sB[threadIdx.x] = yb * yb;
    __syncthreads();
    for (int s = 128; s > 0; s >>= 1) {
        if (threadIdx.x < s) { sA[threadIdx.x] += sA[threadIdx.x+s]; sB[threadIdx.x] += sB[threadIdx.x+s]; }
        __syncthreads();
    }
    if (threadIdx.x == 0) { atomicAdd(&g_stats[6], sA[0]); atomicAdd(&g_stats[7], sB[0]); }
    __syncthreads();
    sA[threadIdx.x] = yi; sB[threadIdx.x] = yi * yi;
    __syncthreads();
    for (int s = 128; s > 0; s >>= 1) {
        if (threadIdx.x < s) { sA[threadIdx.x] += sA[threadIdx.x+s]; sB[threadIdx.x] += sB[threadIdx.x+s]; }
        __syncthreads();
    }
    if (threadIdx.x == 0) { atomicAdd(&g_stats[8], sA[0]); atomicAdd(&g_stats[9], sB[0]); }
}

__global__ void k_out(float* __restrict__ out,
                      const float* __restrict__ fbg, const float* __restrict__ fbb,
                      const float* __restrict__ fig, const float* __restrict__ fib) {
    int t = blockIdx.x * 256 + threadIdx.x;
    float mb = g_stats[6] * (1.0f / NSTAT);
    float vb = g_stats[7] * (1.0f / NSTAT) - mb * mb;
    float nb = fbg[0] * (g_yb[t] - mb) * rsqrtf(vb + 1e-5f) + fbb[0];
    out[t] = silu(nb);

    float mi = g_stats[8] * (1.0f / NSTAT);
    float vi = g_stats[9] * (1.0f / NSTAT) - mi * mi;
    float ni = fig[0] * (g_yi[t] - mi) * rsqrtf(vi + 1e-5f) + fib[0];
    out[NBATCH * NPIX + t] = silu(ni);
}

// ---------------- launch ----------------
extern "C" void kernel_launch(void* const* d_in, const int* in_sizes, int n_in,
                              void* d_out, int out_size) {
    const float* x   = (const float*)d_in[0];
    const float* rw  = (const float*)d_in[1];
    const float* rg  = (const float*)d_in[2];
    const float* rb  = (const float*)d_in[3];
    const float* fbw = (const float*)d_in[4];
    const float* fbg = (const float*)d_in[5];
    const float* fbb = (const float*)d_in[6];
    const float* fiw = (const float*)d_in[7];
    const float* fig = (const float*)d_in[8];
    const float* fib = (const float*)d_in[9];
    float* out = (float*)d_out;

    k_conv<<<NBATCH * 3 * 16, 256>>>(x, rw);
    k_bnsilu<<<32, 256>>>(rg, rb);
    k_opt<<<NPTOT, 64>>>();
    k_post1<<<32, 256>>>(fbw, fiw);
    k_out<<<32, 256>>>(out, fbg, fbb, fig, fib);
}